// round 3
// baseline (speedup 1.0000x reference)
#include <cuda_runtime.h>
#include <cuda_bf16.h>

// Problem constants
#define BB 64
#define SS 2048
#define HH 512
#define H4 128   // H in float4 units

// Scratch (module-scope device globals; no runtime allocation)
__device__ float4 g_P[SS * H4];             // pos_table @ W[0:512]   (4 MB)
__device__ float4 g_N[16 * H4];             // nest_table @ W[512:1024]
__device__ float4 g_G[8 * H4];              // seg_table  @ W[1024:1536]
__device__ unsigned char g_combo[BB * SS];  // (nest<<3)|seg per token

// bf16 split-precision operands for the big GEMM
__device__ __nv_bfloat16 g_Ahi[SS * HH];    // 2 MB
__device__ __nv_bfloat16 g_Alo[SS * HH];    // 2 MB
__device__ __nv_bfloat16 g_Wthi[HH * HH];   // W[0:512]^T  (n-major, k contiguous)
__device__ __nv_bfloat16 g_Wtlo[HH * HH];

// ---------------------------------------------------------------------------
// Kernel 1 "prep": heterogeneous block dispatch.
//   blocks [0,48):      small GEMMs (N & G tables)    — 24 rows x 2 col halves
//   blocks [48,112):    syntax scan (64 batch rows)
//   blocks [112,1136):  split A -> (hi,lo) bf16
//   blocks [1136,1392): split + transpose W[0:512] -> (hi,lo) bf16, n-major
// 256 threads everywhere.
// ---------------------------------------------------------------------------
__global__ void __launch_bounds__(256)
prep_kernel(const int* __restrict__ tok,
            const float* __restrict__ pos,
            const float* __restrict__ nest,
            const float* __restrict__ seg,
            const float* __restrict__ W) {
    const int bid = blockIdx.x;
    const int tid = threadIdx.x;

    if (bid < 48) {
        // ---- small GEMMs: one output row x 256 cols per block ----
        __shared__ float arow[512];
        const int r = bid >> 1;              // 0..23
        const int half = bid & 1;
        const bool is_nest = (r < 16);
        const float* a = is_nest ? (nest + r * 512) : (seg + (r - 16) * 512);
        const float* Wp = W + (is_nest ? 512 * 512 : 1024 * 512);
        float* out = is_nest ? (float*)g_N + r * 512 : (float*)g_G + (r - 16) * 512;

        arow[tid] = a[tid];
        arow[tid + 256] = a[tid + 256];
        __syncthreads();

        const int col = half * 256 + tid;
        float acc = 0.f;
#pragma unroll 8
        for (int k = 0; k < 512; k++)
            acc += arow[k] * Wp[(size_t)k * 512 + col];
        out[col] = acc;
    } else if (bid < 112) {
        // ---- syntax scan: Lindley recursion, 8 tokens / thread ----
        __shared__ int sh_tok[SS];
        __shared__ int agg_sum[256];
        __shared__ int agg_min[256];
        __shared__ int agg_cnt[256];

        const int b = bid - 48;
        const int* t = tok + b * SS;
        for (int i = tid; i < SS; i += 256) sh_tok[i] = t[i];
        __syncthreads();

        const int base = tid * 8;
        int s = 0, mn = 0, cnt = 0;
#pragma unroll
        for (int e = 0; e < 8; e++) {
            int tk = sh_tok[base + e];
            int op = (tk == 40) | (tk == 123) | (tk == 91);
            int cl = (tk == 41) | (tk == 125) | (tk == 93);
            s += op - cl;
            mn = min(mn, s);
            cnt += (tk > 39990);
        }
        agg_sum[tid] = s; agg_min[tid] = mn; agg_cnt[tid] = cnt;
        __syncthreads();

        int S_pre = 0, M_pre = 0, C_pre = 0;
        for (int k = 0; k < tid; k++) {
            M_pre = min(M_pre, S_pre + agg_min[k]);
            S_pre += agg_sum[k];
            C_pre += agg_cnt[k];
        }

        s = S_pre; mn = M_pre; cnt = C_pre;
        unsigned char* out = g_combo + b * SS + base;
#pragma unroll
        for (int e = 0; e < 8; e++) {
            int tk = sh_tok[base + e];
            int op = (tk == 40) | (tk == 123) | (tk == 91);
            int cl = (tk == 41) | (tk == 125) | (tk == 93);
            s += op - cl;
            mn = min(mn, s);
            cnt += (tk > 39990);
            int lvl = min(s - mn, 15);
            out[e] = (unsigned char)((lvl << 3) | (cnt & 7));
        }
    } else if (bid < 1136) {
        // ---- split A: one float4 per thread ----
        const unsigned int i = (bid - 112) * 256u + tid;       // < 262144
        float4 v = ((const float4*)pos)[i];
        float f[4] = {v.x, v.y, v.z, v.w};
        __nv_bfloat16 hi[4], lo[4];
#pragma unroll
        for (int j = 0; j < 4; j++) {
            hi[j] = __float2bfloat16_rn(f[j]);
            lo[j] = __float2bfloat16_rn(f[j] - __bfloat162float(hi[j]));
        }
        ((__nv_bfloat162*)g_Ahi)[i * 2 + 0] = __nv_bfloat162(hi[0], hi[1]);
        ((__nv_bfloat162*)g_Ahi)[i * 2 + 1] = __nv_bfloat162(hi[2], hi[3]);
        ((__nv_bfloat162*)g_Alo)[i * 2 + 0] = __nv_bfloat162(lo[0], lo[1]);
        ((__nv_bfloat162*)g_Alo)[i * 2 + 1] = __nv_bfloat162(lo[2], lo[3]);
    } else {
        // ---- split + transpose W[0:512,:]: one float4 per thread ----
        const unsigned int i = (bid - 1136) * 256u + tid;      // < 65536
        const int k = i >> 7;          // row in W
        const int n4 = i & 127;        // float4 group along n
        float4 v = ((const float4*)W)[i];
        float f[4] = {v.x, v.y, v.z, v.w};
#pragma unroll
        for (int j = 0; j < 4; j++) {
            int n = n4 * 4 + j;
            __nv_bfloat16 hi = __float2bfloat16_rn(f[j]);
            g_Wthi[(size_t)n * 512 + k] = hi;
            g_Wtlo[(size_t)n * 512 + k] =
                __float2bfloat16_rn(f[j] - __bfloat162float(hi));
        }
    }
}

// ---------------------------------------------------------------------------
// Kernel 2: big P GEMM on tensor cores.
// C[2048,512] = A @ W1, split-bf16: Ahi*Whi + Alo*Whi + Ahi*Wlo (virtual K=1536)
// BM=64, BN=64, BK=64 (bf16), 256 threads = 8 warps as 4(m) x 2(n),
// warp tile 16x32 -> 4 x mma.m16n8k16 per k16. fp32 accumulate.
// grid (32, 8) = 256 CTAs.
// ---------------------------------------------------------------------------
#define GSTRIDE 72   // padded smem row stride (bf16) -> conflict-free frag LDS

__global__ void __launch_bounds__(256)
gemm_pos_mma() {
    __shared__ __nv_bfloat16 As[64 * GSTRIDE];
    __shared__ __nv_bfloat16 Bs[64 * GSTRIDE];

    const int tid = threadIdx.x;
    const int wid = tid >> 5;
    const int lane = tid & 31;
    const int m0 = blockIdx.x * 64;
    const int n0 = blockIdx.y * 64;
    const int wm = (wid & 3) * 16;      // warp m offset
    const int wn = (wid >> 2) * 32;     // warp n offset

    // tile-load coords (2 x 16B per array per thread)
    const int lrow = tid >> 3;          // 0..31 (and +32)
    const int lcol = (tid & 7) * 8;     // bf16 col within BK

    float acc[4][4];
#pragma unroll
    for (int j = 0; j < 4; j++)
#pragma unroll
        for (int q = 0; q < 4; q++) acc[j][q] = 0.f;

    const int r = lane >> 2;
    const int c = (lane & 3) * 2;

    uint4 ra0, ra1, rb0, rb1;
    // prefetch tile 0
    {
        const __nv_bfloat16* sA = g_Ahi;
        const __nv_bfloat16* sB = g_Wthi;
        ra0 = *(const uint4*)(sA + (size_t)(m0 + lrow) * 512 + lcol);
        ra1 = *(const uint4*)(sA + (size_t)(m0 + lrow + 32) * 512 + lcol);
        rb0 = *(const uint4*)(sB + (size_t)(n0 + lrow) * 512 + lcol);
        rb1 = *(const uint4*)(sB + (size_t)(n0 + lrow + 32) * 512 + lcol);
    }

#pragma unroll 1
    for (int t = 0; t < 24; t++) {
        __syncthreads();   // prev mma done reading smem
        *(uint4*)(As + lrow * GSTRIDE + lcol) = ra0;
        *(uint4*)(As + (lrow + 32) * GSTRIDE + lcol) = ra1;
        *(uint4*)(Bs + lrow * GSTRIDE + lcol) = rb0;
        *(uint4*)(Bs + (lrow + 32) * GSTRIDE + lcol) = rb1;
        __syncthreads();

        if (t < 23) {   // prefetch next tile; latency hidden behind mma
            const int tn = t + 1;
            const int p = tn >> 3;              // phase: 0 hi*hi, 1 lo*hi, 2 hi*lo
            const int kreal = (tn & 7) * 64;
            const __nv_bfloat16* sA = (p == 1) ? g_Alo : g_Ahi;
            const __nv_bfloat16* sB = (p == 2) ? g_Wtlo : g_Wthi;
            ra0 = *(const uint4*)(sA + (size_t)(m0 + lrow) * 512 + kreal + lcol);
            ra1 = *(const uint4*)(sA + (size_t)(m0 + lrow + 32) * 512 + kreal + lcol);
            rb0 = *(const uint4*)(sB + (size_t)(n0 + lrow) * 512 + kreal + lcol);
            rb1 = *(const uint4*)(sB + (size_t)(n0 + lrow + 32) * 512 + kreal + lcol);
        }

#pragma unroll
        for (int kk = 0; kk < 64; kk += 16) {
            unsigned int a0, a1, a2, a3;
            a0 = *(const unsigned int*)(As + (wm + r) * GSTRIDE + kk + c);
            a1 = *(const unsigned int*)(As + (wm + r + 8) * GSTRIDE + kk + c);
            a2 = *(const unsigned int*)(As + (wm + r) * GSTRIDE + kk + c + 8);
            a3 = *(const unsigned int*)(As + (wm + r + 8) * GSTRIDE + kk + c + 8);
#pragma unroll
            for (int j = 0; j < 4; j++) {
                const int n = wn + j * 8 + r;
                unsigned int b0 = *(const unsigned int*)(Bs + n * GSTRIDE + kk + c);
                unsigned int b1 = *(const unsigned int*)(Bs + n * GSTRIDE + kk + c + 8);
                asm volatile(
                    "mma.sync.aligned.m16n8k16.row.col.f32.bf16.bf16.f32 "
                    "{%0,%1,%2,%3}, {%4,%5,%6,%7}, {%8,%9}, {%0,%1,%2,%3};"
                    : "+f"(acc[j][0]), "+f"(acc[j][1]),
                      "+f"(acc[j][2]), "+f"(acc[j][3])
                    : "r"(a0), "r"(a1), "r"(a2), "r"(a3), "r"(b0), "r"(b1));
            }
        }
    }

    // writeback
    float* C = (float*)g_P;
    const int n2 = (lane & 3) * 2;
#pragma unroll
    for (int j = 0; j < 4; j++) {
        const int col = n0 + wn + j * 8 + n2;
        float* base = C + (size_t)(m0 + wm + r) * 512 + col;
        *(float2*)base = make_float2(acc[j][0], acc[j][1]);
        *(float2*)(base + 8 * 512) = make_float2(acc[j][2], acc[j][3]);
    }
}

// ---------------------------------------------------------------------------
// Kernel 3: combine.  out[b,s,h] = P[s,h] + N[nest,h] + G[seg,h]
// One thread per (s,h4), loops over 8 batches. DRAM-write-bound (256 MB).
// ---------------------------------------------------------------------------
__global__ void __launch_bounds__(256)
combine_kernel(float4* __restrict__ out) {
    unsigned int j = blockIdx.x * 256u + threadIdx.x;
    const int h4 = j & 127;
    const int s = (j >> 7) & 2047;
    const int bo = j >> 18;              // 0..7

    const float4 p = g_P[s * H4 + h4];
#pragma unroll
    for (int bb = 0; bb < 8; bb++) {
        const int b = bo * 8 + bb;
        const unsigned char c = g_combo[b * SS + s];
        const float4 n = g_N[(c >> 3) * H4 + h4];
        const float4 g = g_G[(c & 7) * H4 + h4];
        float4 o;
        o.x = p.x + n.x + g.x;
        o.y = p.y + n.y + g.y;
        o.z = p.z + n.z + g.z;
        o.w = p.w + n.w + g.w;
        out[(((unsigned)b * SS + s) << 7) + h4] = o;
    }
}

// ---------------------------------------------------------------------------
extern "C" void kernel_launch(void* const* d_in, const int* in_sizes, int n_in,
                              void* d_out, int out_size) {
    const int*   tok  = (const int*)d_in[0];    // token_ids [64,2048] int32
    const float* pos  = (const float*)d_in[1];  // pos_table [2048,512]
    const float* nest = (const float*)d_in[2];  // nest_table [16,512]
    const float* seg  = (const float*)d_in[3];  // seg_table [8,512]
    const float* W    = (const float*)d_in[4];  // W [1536,512]
    float4* out = (float4*)d_out;               // [64,2048,512] f32

    prep_kernel<<<1392, 256>>>(tok, pos, nest, seg, W);
    gemm_pos_mma<<<dim3(32, 8), 256>>>();
    combine_kernel<<<(BB * SS * H4 / 8) / 256, 256>>>(out);
}

// round 4
// speedup vs baseline: 1.7840x; 1.7840x over previous
#include <cuda_runtime.h>
#include <cuda_bf16.h>

// Problem constants
#define BB 64
#define SS 2048
#define HH 512
#define H4 128   // H in float4 units

// Scratch (module-scope device globals; no runtime allocation)
__device__ float4 g_P[SS * H4];             // pos_table @ W[0:512]   (4 MB)
__device__ float4 g_N[16 * H4];             // nest_table @ W[512:1024]
__device__ float4 g_G[8 * H4];              // seg_table  @ W[1024:1536]
__device__ unsigned char g_combo[BB * SS];  // (nest<<3)|seg per token

// bf16 split-precision operands for the big GEMM
__device__ __nv_bfloat16 g_Ahi[SS * HH];    // 2 MB
__device__ __nv_bfloat16 g_Alo[SS * HH];    // 2 MB
__device__ __nv_bfloat16 g_Wthi[HH * HH];   // W[0:512]^T  (n-major, k contiguous)
__device__ __nv_bfloat16 g_Wtlo[HH * HH];

// ---------------------------------------------------------------------------
// Kernel: per-row syntax scan. 64 blocks x 128 threads, 16 tokens/thread.
// Lindley recursion via (delta-sum, min-prefix) aggregates.
// ---------------------------------------------------------------------------
__global__ void __launch_bounds__(128)
scan_kernel(const int* __restrict__ tok) {
    __shared__ int sh_tok[SS];
    __shared__ int agg_sum[128];
    __shared__ int agg_min[128];
    __shared__ int agg_cnt[128];

    const int b = blockIdx.x;
    const int* t = tok + b * SS;
    for (int i = threadIdx.x; i < SS; i += 128) sh_tok[i] = t[i];
    __syncthreads();

    const int j = threadIdx.x;
    const int base = j * 16;

    int s = 0, mn = 0, cnt = 0;
#pragma unroll
    for (int e = 0; e < 16; e++) {
        int tk = sh_tok[base + e];
        int op = (tk == 40) | (tk == 123) | (tk == 91);
        int cl = (tk == 41) | (tk == 125) | (tk == 93);
        s += op - cl;
        mn = min(mn, s);
        cnt += (tk > 39990);
    }
    agg_sum[j] = s; agg_min[j] = mn; agg_cnt[j] = cnt;
    __syncthreads();

    int S_pre = 0, M_pre = 0, C_pre = 0;
    for (int k = 0; k < j; k++) {
        M_pre = min(M_pre, S_pre + agg_min[k]);
        S_pre += agg_sum[k];
        C_pre += agg_cnt[k];
    }

    s = S_pre; mn = M_pre; cnt = C_pre;
    unsigned char* out = g_combo + b * SS + base;
#pragma unroll
    for (int e = 0; e < 16; e++) {
        int tk = sh_tok[base + e];
        int op = (tk == 40) | (tk == 123) | (tk == 91);
        int cl = (tk == 41) | (tk == 125) | (tk == 93);
        s += op - cl;
        mn = min(mn, s);
        cnt += (tk > 39990);
        int lvl = min(s - mn, 15);
        out[e] = (unsigned char)((lvl << 3) | (cnt & 7));
    }
}

// ---------------------------------------------------------------------------
// Kernel: small-table GEMMs (N: 16 rows, G: 8 rows).
// grid (24 rows, 4 col-quarters), 256 threads = 128 cols x 2 k-halves.
// Each thread: 256-step k loop, unroll 16 -> high MLP on cold W reads.
// ---------------------------------------------------------------------------
__global__ void __launch_bounds__(256)
gemm_small(const float* __restrict__ nest, const float* __restrict__ seg,
           const float* __restrict__ W) {
    __shared__ float arow[512];
    __shared__ float red[128];

    const int r = blockIdx.x;            // 0..23
    const bool is_nest = (r < 16);
    const float* a = is_nest ? (nest + r * 512) : (seg + (r - 16) * 512);
    const float* Wp = W + (is_nest ? 512 * 512 : 1024 * 512);
    float* out = is_nest ? (float*)g_N + r * 512 : (float*)g_G + (r - 16) * 512;

    const int tid = threadIdx.x;
    arow[tid] = a[tid];
    arow[tid + 256] = a[tid + 256];
    __syncthreads();

    const int col = blockIdx.y * 128 + (tid & 127);
    const int kh = tid >> 7;             // 0/1: k-half
    const float* wcol = Wp + (size_t)(kh * 256) * 512 + col;
    const float* ar = arow + kh * 256;

    float acc = 0.f;
#pragma unroll 16
    for (int k = 0; k < 256; k++)
        acc += ar[k] * wcol[(size_t)k * 512];

    if (kh) red[tid - 128] = acc;
    __syncthreads();
    if (!kh) out[col] = acc + red[tid];
}

// ---------------------------------------------------------------------------
// Kernel: split pos_table -> (hi, lo) bf16.  1024 blocks x 256, 1 float4/thr.
// ---------------------------------------------------------------------------
__global__ void __launch_bounds__(256)
splitA_kernel(const float* __restrict__ pos) {
    const unsigned int i = blockIdx.x * 256u + threadIdx.x;   // < 262144
    float4 v = ((const float4*)pos)[i];
    float f[4] = {v.x, v.y, v.z, v.w};
    __nv_bfloat16 hi[4], lo[4];
#pragma unroll
    for (int j = 0; j < 4; j++) {
        hi[j] = __float2bfloat16_rn(f[j]);
        lo[j] = __float2bfloat16_rn(f[j] - __bfloat162float(hi[j]));
    }
    ((__nv_bfloat162*)g_Ahi)[i * 2 + 0] = __nv_bfloat162(hi[0], hi[1]);
    ((__nv_bfloat162*)g_Ahi)[i * 2 + 1] = __nv_bfloat162(hi[2], hi[3]);
    ((__nv_bfloat162*)g_Alo)[i * 2 + 0] = __nv_bfloat162(lo[0], lo[1]);
    ((__nv_bfloat162*)g_Alo)[i * 2 + 1] = __nv_bfloat162(lo[2], lo[3]);
}

// ---------------------------------------------------------------------------
// Kernel: split + transpose W[0:512,:] -> (hi, lo) bf16, n-major.
// 256 blocks x 256, 1 float4/thread, scattered 2B stores (sector-bound, ~3us).
// ---------------------------------------------------------------------------
__global__ void __launch_bounds__(256)
splitW_kernel(const float* __restrict__ W) {
    const unsigned int i = blockIdx.x * 256u + threadIdx.x;   // < 65536
    const int k = i >> 7;          // row in W
    const int n4 = i & 127;        // float4 group along n
    float4 v = ((const float4*)W)[i];
    float f[4] = {v.x, v.y, v.z, v.w};
#pragma unroll
    for (int j = 0; j < 4; j++) {
        int n = n4 * 4 + j;
        __nv_bfloat16 hi = __float2bfloat16_rn(f[j]);
        g_Wthi[(size_t)n * 512 + k] = hi;
        g_Wtlo[(size_t)n * 512 + k] =
            __float2bfloat16_rn(f[j] - __bfloat162float(hi));
    }
}

// ---------------------------------------------------------------------------
// Kernel: big P GEMM on tensor cores.
// C[2048,512] = A @ W1, split-bf16: Ahi*Whi + Alo*Whi + Ahi*Wlo (virtual K=1536)
// BM=64, BN=64, BK=64 (bf16), 256 threads = 8 warps 4(m) x 2(n),
// warp tile 16x32 -> 4 x mma.m16n8k16 per k16. fp32 accumulate. grid (32,8).
// ---------------------------------------------------------------------------
#define GSTRIDE 72   // padded smem row stride (bf16)

__global__ void __launch_bounds__(256)
gemm_pos_mma() {
    __shared__ __nv_bfloat16 As[64 * GSTRIDE];
    __shared__ __nv_bfloat16 Bs[64 * GSTRIDE];

    const int tid = threadIdx.x;
    const int wid = tid >> 5;
    const int lane = tid & 31;
    const int m0 = blockIdx.x * 64;
    const int n0 = blockIdx.y * 64;
    const int wm = (wid & 3) * 16;
    const int wn = (wid >> 2) * 32;

    const int lrow = tid >> 3;
    const int lcol = (tid & 7) * 8;

    float acc[4][4];
#pragma unroll
    for (int j = 0; j < 4; j++)
#pragma unroll
        for (int q = 0; q < 4; q++) acc[j][q] = 0.f;

    const int r = lane >> 2;
    const int c = (lane & 3) * 2;

    uint4 ra0, ra1, rb0, rb1;
    {
        const __nv_bfloat16* sA = g_Ahi;
        const __nv_bfloat16* sB = g_Wthi;
        ra0 = *(const uint4*)(sA + (size_t)(m0 + lrow) * 512 + lcol);
        ra1 = *(const uint4*)(sA + (size_t)(m0 + lrow + 32) * 512 + lcol);
        rb0 = *(const uint4*)(sB + (size_t)(n0 + lrow) * 512 + lcol);
        rb1 = *(const uint4*)(sB + (size_t)(n0 + lrow + 32) * 512 + lcol);
    }

#pragma unroll 1
    for (int t = 0; t < 24; t++) {
        __syncthreads();
        *(uint4*)(As + lrow * GSTRIDE + lcol) = ra0;
        *(uint4*)(As + (lrow + 32) * GSTRIDE + lcol) = ra1;
        *(uint4*)(Bs + lrow * GSTRIDE + lcol) = rb0;
        *(uint4*)(Bs + (lrow + 32) * GSTRIDE + lcol) = rb1;
        __syncthreads();

        if (t < 23) {
            const int tn = t + 1;
            const int p = tn >> 3;              // 0 hi*hi, 1 lo*hi, 2 hi*lo
            const int kreal = (tn & 7) * 64;
            const __nv_bfloat16* sA = (p == 1) ? g_Alo : g_Ahi;
            const __nv_bfloat16* sB = (p == 2) ? g_Wtlo : g_Wthi;
            ra0 = *(const uint4*)(sA + (size_t)(m0 + lrow) * 512 + kreal + lcol);
            ra1 = *(const uint4*)(sA + (size_t)(m0 + lrow + 32) * 512 + kreal + lcol);
            rb0 = *(const uint4*)(sB + (size_t)(n0 + lrow) * 512 + kreal + lcol);
            rb1 = *(const uint4*)(sB + (size_t)(n0 + lrow + 32) * 512 + kreal + lcol);
        }

#pragma unroll
        for (int kk = 0; kk < 64; kk += 16) {
            unsigned int a0, a1, a2, a3;
            a0 = *(const unsigned int*)(As + (wm + r) * GSTRIDE + kk + c);
            a1 = *(const unsigned int*)(As + (wm + r + 8) * GSTRIDE + kk + c);
            a2 = *(const unsigned int*)(As + (wm + r) * GSTRIDE + kk + c + 8);
            a3 = *(const unsigned int*)(As + (wm + r + 8) * GSTRIDE + kk + c + 8);
#pragma unroll
            for (int j = 0; j < 4; j++) {
                const int n = wn + j * 8 + r;
                unsigned int b0 = *(const unsigned int*)(Bs + n * GSTRIDE + kk + c);
                unsigned int b1 = *(const unsigned int*)(Bs + n * GSTRIDE + kk + c + 8);
                asm volatile(
                    "mma.sync.aligned.m16n8k16.row.col.f32.bf16.bf16.f32 "
                    "{%0,%1,%2,%3}, {%4,%5,%6,%7}, {%8,%9}, {%0,%1,%2,%3};"
                    : "+f"(acc[j][0]), "+f"(acc[j][1]),
                      "+f"(acc[j][2]), "+f"(acc[j][3])
                    : "r"(a0), "r"(a1), "r"(a2), "r"(a3), "r"(b0), "r"(b1));
            }
        }
    }

    float* C = (float*)g_P;
    const int n2 = (lane & 3) * 2;
#pragma unroll
    for (int j = 0; j < 4; j++) {
        const int col = n0 + wn + j * 8 + n2;
        float* base = C + (size_t)(m0 + wm + r) * 512 + col;
        *(float2*)base = make_float2(acc[j][0], acc[j][1]);
        *(float2*)(base + 8 * 512) = make_float2(acc[j][2], acc[j][3]);
    }
}

// ---------------------------------------------------------------------------
// Kernel: combine.  out[b,s,h] = P[s,h] + N[nest,h] + G[seg,h]
// One thread per (s,h4), loops over 8 batches. DRAM-write-bound (256 MB).
// ---------------------------------------------------------------------------
__global__ void __launch_bounds__(256)
combine_kernel(float4* __restrict__ out) {
    unsigned int j = blockIdx.x * 256u + threadIdx.x;
    const int h4 = j & 127;
    const int s = (j >> 7) & 2047;
    const int bo = j >> 18;              // 0..7

    const float4 p = g_P[s * H4 + h4];
#pragma unroll
    for (int bb = 0; bb < 8; bb++) {
        const int b = bo * 8 + bb;
        const unsigned char c = g_combo[b * SS + s];
        const float4 n = g_N[(c >> 3) * H4 + h4];
        const float4 g = g_G[(c & 7) * H4 + h4];
        float4 o;
        o.x = p.x + n.x + g.x;
        o.y = p.y + n.y + g.y;
        o.z = p.z + n.z + g.z;
        o.w = p.w + n.w + g.w;
        out[(((unsigned)b * SS + s) << 7) + h4] = o;
    }
}

// ---------------------------------------------------------------------------
extern "C" void kernel_launch(void* const* d_in, const int* in_sizes, int n_in,
                              void* d_out, int out_size) {
    const int*   tok  = (const int*)d_in[0];    // token_ids [64,2048] int32
    const float* pos  = (const float*)d_in[1];  // pos_table [2048,512]
    const float* nest = (const float*)d_in[2];  // nest_table [16,512]
    const float* seg  = (const float*)d_in[3];  // seg_table [8,512]
    const float* W    = (const float*)d_in[4];  // W [1536,512]
    float4* out = (float4*)d_out;               // [64,2048,512] f32

    splitW_kernel<<<256, 256>>>(W);
    splitA_kernel<<<1024, 256>>>(pos);
    scan_kernel<<<BB, 128>>>(tok);
    gemm_small<<<dim3(24, 4), 256>>>(nest, seg, W);
    gemm_pos_mma<<<dim3(32, 8), 256>>>();
    combine_kernel<<<(BB * SS * H4 / 8) / 256, 256>>>(out);
}

// round 5
// speedup vs baseline: 1.9542x; 1.0954x over previous
#include <cuda_runtime.h>
#include <cuda_bf16.h>

// Problem constants
#define BB 64
#define SS 2048
#define HH 512
#define H4 128   // H in float4 units

// Scratch (module-scope device globals; no runtime allocation)
__device__ float4 g_P[SS * H4];             // pos_table @ W[0:512]   (4 MB)
__device__ float4 g_N[16 * H4];             // nest_table @ W[512:1024]
__device__ float4 g_G[8 * H4];              // seg_table  @ W[1024:1536]
__device__ unsigned char g_combo[BB * SS];  // (nest<<3)|seg per token

// bf16 split-precision operands for the big GEMM
__device__ __nv_bfloat16 g_Ahi[SS * HH];    // 2 MB
__device__ __nv_bfloat16 g_Alo[SS * HH];    // 2 MB
__device__ __nv_bfloat16 g_Wthi[HH * HH];   // W[0:512]^T  (n-major, k contiguous)
__device__ __nv_bfloat16 g_Wtlo[HH * HH];

// ---------------------------------------------------------------------------
// Kernel 1 "prep": splitW (256 blks) + splitA (1024 blks) + scan (64 blks).
// All branches simple & bandwidth/latency friendly; union reg budget is safe.
// ---------------------------------------------------------------------------
__global__ void __launch_bounds__(256)
prep_kernel(const int* __restrict__ tok,
            const float* __restrict__ pos,
            const float* __restrict__ W) {
    const int bid = blockIdx.x;
    const int tid = threadIdx.x;

    if (bid < 256) {
        // ---- split + transpose W[0:512,:] -> (hi,lo) bf16, n-major ----
        const unsigned int i = bid * 256u + tid;      // < 65536
        const int k = i >> 7;
        const int n4 = i & 127;
        float4 v = ((const float4*)W)[i];
        float f[4] = {v.x, v.y, v.z, v.w};
#pragma unroll
        for (int j = 0; j < 4; j++) {
            int n = n4 * 4 + j;
            __nv_bfloat16 hi = __float2bfloat16_rn(f[j]);
            g_Wthi[(size_t)n * 512 + k] = hi;
            g_Wtlo[(size_t)n * 512 + k] =
                __float2bfloat16_rn(f[j] - __bfloat162float(hi));
        }
    } else if (bid < 1280) {
        // ---- split pos_table -> (hi,lo) bf16; one float4/thread ----
        const unsigned int i = (bid - 256) * 256u + tid;   // < 262144
        float4 v = ((const float4*)pos)[i];
        float f[4] = {v.x, v.y, v.z, v.w};
        __nv_bfloat16 hi[4], lo[4];
#pragma unroll
        for (int j = 0; j < 4; j++) {
            hi[j] = __float2bfloat16_rn(f[j]);
            lo[j] = __float2bfloat16_rn(f[j] - __bfloat162float(hi[j]));
        }
        ((__nv_bfloat162*)g_Ahi)[i * 2 + 0] = __nv_bfloat162(hi[0], hi[1]);
        ((__nv_bfloat162*)g_Ahi)[i * 2 + 1] = __nv_bfloat162(hi[2], hi[3]);
        ((__nv_bfloat162*)g_Alo)[i * 2 + 0] = __nv_bfloat162(lo[0], lo[1]);
        ((__nv_bfloat162*)g_Alo)[i * 2 + 1] = __nv_bfloat162(lo[2], lo[3]);
    } else {
        // ---- syntax scan: Lindley recursion, 8 tokens / thread ----
        __shared__ int sh_tok[SS];
        __shared__ int agg_sum[256];
        __shared__ int agg_min[256];
        __shared__ int agg_cnt[256];

        const int b = bid - 1280;
        const int* t = tok + b * SS;
        for (int i = tid; i < SS; i += 256) sh_tok[i] = t[i];
        __syncthreads();

        const int base = tid * 8;
        int s = 0, mn = 0, cnt = 0;
#pragma unroll
        for (int e = 0; e < 8; e++) {
            int tk = sh_tok[base + e];
            int op = (tk == 40) | (tk == 123) | (tk == 91);
            int cl = (tk == 41) | (tk == 125) | (tk == 93);
            s += op - cl;
            mn = min(mn, s);
            cnt += (tk > 39990);
        }
        agg_sum[tid] = s; agg_min[tid] = mn; agg_cnt[tid] = cnt;
        __syncthreads();

        int S_pre = 0, M_pre = 0, C_pre = 0;
        for (int k = 0; k < tid; k++) {
            M_pre = min(M_pre, S_pre + agg_min[k]);
            S_pre += agg_sum[k];
            C_pre += agg_cnt[k];
        }

        s = S_pre; mn = M_pre; cnt = C_pre;
        unsigned char* out = g_combo + b * SS + base;
#pragma unroll
        for (int e = 0; e < 8; e++) {
            int tk = sh_tok[base + e];
            int op = (tk == 40) | (tk == 123) | (tk == 91);
            int cl = (tk == 41) | (tk == 125) | (tk == 93);
            s += op - cl;
            mn = min(mn, s);
            cnt += (tk > 39990);
            int lvl = min(s - mn, 15);
            out[e] = (unsigned char)((lvl << 3) | (cnt & 7));
        }
    }
}

// ---------------------------------------------------------------------------
// Kernel 2 "gemm_fused": blocks [0,96) = small-table GEMMs (run concurrently,
// hidden under the mma wave); blocks [96,352) = bf16-MMA P GEMM.
// ---------------------------------------------------------------------------
#define GSTRIDE 72   // padded smem row stride (bf16)

__global__ void __launch_bounds__(256)
gemm_fused(const float* __restrict__ nest, const float* __restrict__ seg,
           const float* __restrict__ W) {
    __shared__ __nv_bfloat16 As[64 * GSTRIDE];
    __shared__ __nv_bfloat16 Bs[64 * GSTRIDE];

    const int tid = threadIdx.x;

    if (blockIdx.x < 96) {
        // ================= small-table GEMMs =================
        // grid-part (24 rows x 4 col-quarters); 256 thr = 128 cols x 2 k-halves
        float* arow = (float*)As;                 // reuse smem
        float* red = (float*)Bs;

        const int r = blockIdx.x >> 2;            // 0..23
        const int quarter = blockIdx.x & 3;
        const bool is_nest = (r < 16);
        const float* a = is_nest ? (nest + r * 512) : (seg + (r - 16) * 512);
        const float* Wp = W + (is_nest ? 512 * 512 : 1024 * 512);
        float* out = is_nest ? (float*)g_N + r * 512
                             : (float*)g_G + (r - 16) * 512;

        arow[tid] = a[tid];
        arow[tid + 256] = a[tid + 256];
        __syncthreads();

        const int col = quarter * 128 + (tid & 127);
        const int kh = tid >> 7;
        const float* wcol = Wp + (size_t)(kh * 256) * 512 + col;
        const float* ar = arow + kh * 256;

        float acc = 0.f;
#pragma unroll 16
        for (int k = 0; k < 256; k++)
            acc += ar[k] * wcol[(size_t)k * 512];

        if (kh) red[tid - 128] = acc;
        __syncthreads();
        if (!kh) out[col] = acc + red[tid];
        return;
    }

    // ================= bf16-MMA P GEMM =================
    // C[2048,512] = A @ W1, split-bf16 (virtual K = 1536), fp32 accumulate.
    const int q = blockIdx.x - 96;      // 0..255
    const int m0 = (q & 31) * 64;
    const int n0 = (q >> 5) * 64;

    const int wid = tid >> 5;
    const int lane = tid & 31;
    const int wm = (wid & 3) * 16;
    const int wn = (wid >> 2) * 32;

    const int lrow = tid >> 3;
    const int lcol = (tid & 7) * 8;

    float acc[4][4];
#pragma unroll
    for (int j = 0; j < 4; j++)
#pragma unroll
        for (int p = 0; p < 4; p++) acc[j][p] = 0.f;

    const int r = lane >> 2;
    const int c = (lane & 3) * 2;

    uint4 ra0, ra1, rb0, rb1;
    {
        const __nv_bfloat16* sA = g_Ahi;
        const __nv_bfloat16* sB = g_Wthi;
        ra0 = *(const uint4*)(sA + (size_t)(m0 + lrow) * 512 + lcol);
        ra1 = *(const uint4*)(sA + (size_t)(m0 + lrow + 32) * 512 + lcol);
        rb0 = *(const uint4*)(sB + (size_t)(n0 + lrow) * 512 + lcol);
        rb1 = *(const uint4*)(sB + (size_t)(n0 + lrow + 32) * 512 + lcol);
    }

#pragma unroll 1
    for (int t = 0; t < 24; t++) {
        __syncthreads();
        *(uint4*)(As + lrow * GSTRIDE + lcol) = ra0;
        *(uint4*)(As + (lrow + 32) * GSTRIDE + lcol) = ra1;
        *(uint4*)(Bs + lrow * GSTRIDE + lcol) = rb0;
        *(uint4*)(Bs + (lrow + 32) * GSTRIDE + lcol) = rb1;
        __syncthreads();

        if (t < 23) {
            const int tn = t + 1;
            const int p = tn >> 3;              // 0 hi*hi, 1 lo*hi, 2 hi*lo
            const int kreal = (tn & 7) * 64;
            const __nv_bfloat16* sA = (p == 1) ? g_Alo : g_Ahi;
            const __nv_bfloat16* sB = (p == 2) ? g_Wtlo : g_Wthi;
            ra0 = *(const uint4*)(sA + (size_t)(m0 + lrow) * 512 + kreal + lcol);
            ra1 = *(const uint4*)(sA + (size_t)(m0 + lrow + 32) * 512 + kreal + lcol);
            rb0 = *(const uint4*)(sB + (size_t)(n0 + lrow) * 512 + kreal + lcol);
            rb1 = *(const uint4*)(sB + (size_t)(n0 + lrow + 32) * 512 + kreal + lcol);
        }

#pragma unroll
        for (int kk = 0; kk < 64; kk += 16) {
            unsigned int a0, a1, a2, a3;
            a0 = *(const unsigned int*)(As + (wm + r) * GSTRIDE + kk + c);
            a1 = *(const unsigned int*)(As + (wm + r + 8) * GSTRIDE + kk + c);
            a2 = *(const unsigned int*)(As + (wm + r) * GSTRIDE + kk + c + 8);
            a3 = *(const unsigned int*)(As + (wm + r + 8) * GSTRIDE + kk + c + 8);
#pragma unroll
            for (int j = 0; j < 4; j++) {
                const int n = wn + j * 8 + r;
                unsigned int b0 = *(const unsigned int*)(Bs + n * GSTRIDE + kk + c);
                unsigned int b1 = *(const unsigned int*)(Bs + n * GSTRIDE + kk + c + 8);
                asm volatile(
                    "mma.sync.aligned.m16n8k16.row.col.f32.bf16.bf16.f32 "
                    "{%0,%1,%2,%3}, {%4,%5,%6,%7}, {%8,%9}, {%0,%1,%2,%3};"
                    : "+f"(acc[j][0]), "+f"(acc[j][1]),
                      "+f"(acc[j][2]), "+f"(acc[j][3])
                    : "r"(a0), "r"(a1), "r"(a2), "r"(a3), "r"(b0), "r"(b1));
            }
        }
    }

    float* C = (float*)g_P;
    const int n2 = (lane & 3) * 2;
#pragma unroll
    for (int j = 0; j < 4; j++) {
        const int col = n0 + wn + j * 8 + n2;
        float* base = C + (size_t)(m0 + wm + r) * 512 + col;
        *(float2*)base = make_float2(acc[j][0], acc[j][1]);
        *(float2*)(base + 8 * 512) = make_float2(acc[j][2], acc[j][3]);
    }
}

// ---------------------------------------------------------------------------
// Kernel 3: combine.  out[b,s,h] = P[s,h] + N[nest,h] + G[seg,h]
// One thread per (s,h4); loops over ALL 64 batches -> P read exactly once.
// combo load is warp-uniform (broadcast). DRAM-write-bound (256 MB out).
// ---------------------------------------------------------------------------
__global__ void __launch_bounds__(256)
combine_kernel(float4* __restrict__ out) {
    const unsigned int j = blockIdx.x * 256u + threadIdx.x;  // < 262144
    const int h4 = j & 127;
    const int s = j >> 7;            // 0..2047

    const float4 p = g_P[s * H4 + h4];
    const unsigned char* combo = g_combo + s;
#pragma unroll 8
    for (int b = 0; b < BB; b++) {
        const unsigned char c = combo[b * SS];
        const float4 n = g_N[(c >> 3) * H4 + h4];
        const float4 g = g_G[(c & 7) * H4 + h4];
        float4 o;
        o.x = p.x + n.x + g.x;
        o.y = p.y + n.y + g.y;
        o.z = p.z + n.z + g.z;
        o.w = p.w + n.w + g.w;
        out[(((unsigned)b * SS + s) << 7) + h4] = o;
    }
}

// ---------------------------------------------------------------------------
extern "C" void kernel_launch(void* const* d_in, const int* in_sizes, int n_in,
                              void* d_out, int out_size) {
    const int*   tok  = (const int*)d_in[0];    // token_ids [64,2048] int32
    const float* pos  = (const float*)d_in[1];  // pos_table [2048,512]
    const float* nest = (const float*)d_in[2];  // nest_table [16,512]
    const float* seg  = (const float*)d_in[3];  // seg_table [8,512]
    const float* W    = (const float*)d_in[4];  // W [1536,512]
    float4* out = (float4*)d_out;               // [64,2048,512] f32

    prep_kernel<<<1344, 256>>>(tok, pos, W);
    gemm_fused<<<96 + 256, 256>>>(nest, seg, W);
    combine_kernel<<<SS * H4 / 256, 256>>>(out);
}

// round 6
// speedup vs baseline: 2.3554x; 1.2053x over previous
#include <cuda_runtime.h>
#include <cuda_bf16.h>

// Problem constants
#define BB 64
#define SS 2048
#define HH 512
#define H4 128   // H in float4 units

// Scratch (module-scope device globals; no runtime allocation)
__device__ float4 g_P[SS * H4];             // pos_table @ W[0:512]   (4 MB)
__device__ float4 g_N[16 * H4];             // nest_table @ W[512:1024]
__device__ float4 g_G[8 * H4];              // seg_table  @ W[1024:1536]
__device__ unsigned char g_combo[BB * SS];  // (nest<<3)|seg per token

// bf16 split-precision operands for the big GEMM
__device__ __nv_bfloat16 g_Ahi[SS * HH];    // 2 MB
__device__ __nv_bfloat16 g_Alo[SS * HH];    // 2 MB
__device__ __nv_bfloat16 g_Wthi[HH * HH];   // W[0:512]^T  (n-major, k contiguous)
__device__ __nv_bfloat16 g_Wtlo[HH * HH];

// ---------------------------------------------------------------------------
// Small-GEMM body: one CTA handles a 32-col chunk of ALL R rows of a table.
// 256 threads = 32 cols x 8 k-eighths; each thread accumulates R rows.
// W read exactly once per chunk; arow reads are warp-broadcast.
// ---------------------------------------------------------------------------
template <int R>
__device__ __forceinline__ void small_gemm_body(
    const float* __restrict__ a, const float* __restrict__ Wp,
    float* __restrict__ outp, int colbase, float* sbuf, int tid) {
    float* arow = sbuf;                       // R*512 floats
    for (int i = tid; i < R * 512; i += 256) arow[i] = a[i];
    __syncthreads();

    const int c = tid & 31;
    const int kg = tid >> 5;                  // 0..7
    const int col = colbase + c;
    const float* wptr = Wp + (size_t)(kg * 64) * 512 + col;
    const float* ar = arow + kg * 64;

    float acc[R];
#pragma unroll
    for (int r = 0; r < R; r++) acc[r] = 0.f;

#pragma unroll 1
    for (int kk = 0; kk < 64; kk += 8) {
        float w[8];
#pragma unroll
        for (int u = 0; u < 8; u++) w[u] = wptr[(size_t)(kk + u) * 512];
#pragma unroll
        for (int u = 0; u < 8; u++)
#pragma unroll
            for (int r = 0; r < R; r++)
                acc[r] += ar[r * 512 + kk + u] * w[u];
    }

    __syncthreads();                          // all arow reads done
    float* red = sbuf;                        // reuse: 8*R*32 floats
#pragma unroll
    for (int r = 0; r < R; r++)
        red[(kg * R + r) * 32 + c] = acc[r];
    __syncthreads();

    for (int p = tid; p < R * 32; p += 256) {
        const int r = p >> 5, cc = p & 31;
        float s = 0.f;
#pragma unroll
        for (int g = 0; g < 8; g++) s += red[(g * R + r) * 32 + cc];
        outp[r * 512 + colbase + cc] = s;
    }
}

// ---------------------------------------------------------------------------
// Kernel 1 "prep": heterogeneous, 416 blocks x 256 threads.
//   [0,64):    W split+transpose via smem tile (coalesced both directions)
//   [64,320):  split pos_table -> (hi,lo) bf16, 4 float4/thread
//   [320,384): syntax scan, warp-shuffle parallel Lindley prefix
//   [384,416): small-table GEMMs (N: 16 chunks, G: 16 chunks)
// Shared buffer: 32 KB union across branches.
// ---------------------------------------------------------------------------
__global__ void __launch_bounds__(256)
prep_kernel(const int* __restrict__ tok,
            const float* __restrict__ pos,
            const float* __restrict__ nest,
            const float* __restrict__ seg,
            const float* __restrict__ W) {
    __shared__ float sbuf[8192];              // 32 KB
    const int bid = blockIdx.x;
    const int tid = threadIdx.x;

    if (bid < 64) {
        // ---- W[0:512] split + transpose: 8x8 tiles of 64x64 ----
        const int ki = bid >> 3, ni = bid & 7;
        float* St = sbuf;                     // 64 x 65
#pragma unroll
        for (int l = 0; l < 4; l++) {
            const int idx = tid + l * 256;    // 0..1023
            const int kr = idx >> 4;
            const int c4 = idx & 15;
            float4 v = *(const float4*)(W + (size_t)(ki * 64 + kr) * 512 + ni * 64 + c4 * 4);
            St[kr * 65 + c4 * 4 + 0] = v.x;
            St[kr * 65 + c4 * 4 + 1] = v.y;
            St[kr * 65 + c4 * 4 + 2] = v.z;
            St[kr * 65 + c4 * 4 + 3] = v.w;
        }
        __syncthreads();

        const int n = tid >> 2;               // 0..63
        const int kg = tid & 3;               // 16-k group
        __align__(16) __nv_bfloat162 hiu[8];
        __align__(16) __nv_bfloat162 lou[8];
#pragma unroll
        for (int e = 0; e < 16; e += 2) {
            float f0 = St[(kg * 16 + e) * 65 + n];
            float f1 = St[(kg * 16 + e + 1) * 65 + n];
            __nv_bfloat16 h0 = __float2bfloat16_rn(f0);
            __nv_bfloat16 h1 = __float2bfloat16_rn(f1);
            __nv_bfloat16 l0 = __float2bfloat16_rn(f0 - __bfloat162float(h0));
            __nv_bfloat16 l1 = __float2bfloat16_rn(f1 - __bfloat162float(h1));
            hiu[e >> 1] = __nv_bfloat162(h0, h1);
            lou[e >> 1] = __nv_bfloat162(l0, l1);
        }
        const size_t off = (size_t)(ni * 64 + n) * 512 + ki * 64 + kg * 16;
        *(uint4*)(g_Wthi + off) = ((uint4*)hiu)[0];
        *(uint4*)(g_Wthi + off + 8) = ((uint4*)hiu)[1];
        *(uint4*)(g_Wtlo + off) = ((uint4*)lou)[0];
        *(uint4*)(g_Wtlo + off + 8) = ((uint4*)lou)[1];
    } else if (bid < 320) {
        // ---- split pos_table -> (hi,lo); 4 float4 per thread ----
        const unsigned int base = (bid - 64) * 1024u;
#pragma unroll
        for (int l = 0; l < 4; l++) {
            const unsigned int i = base + tid + l * 256u;   // < 262144
            float4 v = ((const float4*)pos)[i];
            float f[4] = {v.x, v.y, v.z, v.w};
            __nv_bfloat16 hi[4], lo[4];
#pragma unroll
            for (int j = 0; j < 4; j++) {
                hi[j] = __float2bfloat16_rn(f[j]);
                lo[j] = __float2bfloat16_rn(f[j] - __bfloat162float(hi[j]));
            }
            ((__nv_bfloat162*)g_Ahi)[i * 2 + 0] = __nv_bfloat162(hi[0], hi[1]);
            ((__nv_bfloat162*)g_Ahi)[i * 2 + 1] = __nv_bfloat162(hi[2], hi[3]);
            ((__nv_bfloat162*)g_Alo)[i * 2 + 0] = __nv_bfloat162(lo[0], lo[1]);
            ((__nv_bfloat162*)g_Alo)[i * 2 + 1] = __nv_bfloat162(lo[2], lo[3]);
        }
    } else if (bid < 384) {
        // ---- syntax scan with warp-shuffle parallel prefix ----
        int* sh_tok = (int*)sbuf;             // 2048 ints
        int* wsum = (int*)sbuf + 2048;
        int* wmin = wsum + 8;
        int* wcnt = wmin + 8;

        const int b = bid - 320;
        const int* t = tok + b * SS;
        for (int i = tid; i < SS; i += 256) sh_tok[i] = t[i];
        __syncthreads();

        const int base = tid * 8;
        int s = 0, mn = 0, cnt = 0;
#pragma unroll
        for (int e = 0; e < 8; e++) {
            int tk = sh_tok[base + e];
            int op = (tk == 40) | (tk == 123) | (tk == 91);
            int cl = (tk == 41) | (tk == 125) | (tk == 93);
            s += op - cl;
            mn = min(mn, s);
            cnt += (tk > 39990);
        }

        // warp inclusive scan of (S, M, C); combine: (S1+S2, min(M1, S1+M2))
        const int lane = tid & 31;
        const int wid = tid >> 5;
        int Si = s, Mi = mn, Ci = cnt;
#pragma unroll
        for (int d = 1; d < 32; d <<= 1) {
            int So = __shfl_up_sync(0xffffffffu, Si, d);
            int Mo = __shfl_up_sync(0xffffffffu, Mi, d);
            int Co = __shfl_up_sync(0xffffffffu, Ci, d);
            if (lane >= d) { Mi = min(Mo, So + Mi); Si = So + Si; Ci = Co + Ci; }
        }
        if (lane == 31) { wsum[wid] = Si; wmin[wid] = Mi; wcnt[wid] = Ci; }

        // exclusive within warp
        int Se = __shfl_up_sync(0xffffffffu, Si, 1);
        int Me = __shfl_up_sync(0xffffffffu, Mi, 1);
        int Ce = __shfl_up_sync(0xffffffffu, Ci, 1);
        if (lane == 0) { Se = 0; Me = 0; Ce = 0; }
        __syncthreads();

        // combine previous warps (max 8 iters)
        int Sw = 0, Mw = 0, Cw = 0;
        for (int w = 0; w < wid; w++) {
            Mw = min(Mw, Sw + wmin[w]);
            Sw += wsum[w];
            Cw += wcnt[w];
        }
        int S_pre = Sw + Se;
        int M_pre = min(Mw, Sw + Me);
        int C_pre = Cw + Ce;

        // replay
        s = S_pre; mn = M_pre; cnt = C_pre;
        unsigned char* out = g_combo + b * SS + base;
#pragma unroll
        for (int e = 0; e < 8; e++) {
            int tk = sh_tok[base + e];
            int op = (tk == 40) | (tk == 123) | (tk == 91);
            int cl = (tk == 41) | (tk == 125) | (tk == 93);
            s += op - cl;
            mn = min(mn, s);
            cnt += (tk > 39990);
            int lvl = min(s - mn, 15);
            out[e] = (unsigned char)((lvl << 3) | (cnt & 7));
        }
    } else {
        // ---- small-table GEMMs; W read once per chunk ----
        const int tb = bid - 384;             // 0..31
        const int colbase = (tb & 15) * 32;
        if (tb < 16)
            small_gemm_body<16>(nest, W + 512 * 512, (float*)g_N, colbase, sbuf, tid);
        else
            small_gemm_body<8>(seg, W + 1024 * 512, (float*)g_G, colbase, sbuf, tid);
    }
}

// ---------------------------------------------------------------------------
// Kernel 2: pure bf16-MMA P GEMM (256 CTAs).
// C[2048,512] = A @ W1, split-bf16: Ahi*Whi + Alo*Whi + Ahi*Wlo (virtual K=1536)
// BM=64, BN=64, BK=64, 256 threads = 8 warps 4(m) x 2(n), fp32 accumulate.
// ---------------------------------------------------------------------------
#define GSTRIDE 72   // padded smem row stride (bf16)

__global__ void __launch_bounds__(256)
gemm_pos_mma() {
    __shared__ __nv_bfloat16 As[64 * GSTRIDE];
    __shared__ __nv_bfloat16 Bs[64 * GSTRIDE];

    const int tid = threadIdx.x;
    const int q = blockIdx.x;
    const int m0 = (q & 31) * 64;
    const int n0 = (q >> 5) * 64;

    const int wid = tid >> 5;
    const int lane = tid & 31;
    const int wm = (wid & 3) * 16;
    const int wn = (wid >> 2) * 32;

    const int lrow = tid >> 3;
    const int lcol = (tid & 7) * 8;

    float acc[4][4];
#pragma unroll
    for (int j = 0; j < 4; j++)
#pragma unroll
        for (int p = 0; p < 4; p++) acc[j][p] = 0.f;

    const int r = lane >> 2;
    const int c = (lane & 3) * 2;

    uint4 ra0, ra1, rb0, rb1;
    {
        const __nv_bfloat16* sA = g_Ahi;
        const __nv_bfloat16* sB = g_Wthi;
        ra0 = *(const uint4*)(sA + (size_t)(m0 + lrow) * 512 + lcol);
        ra1 = *(const uint4*)(sA + (size_t)(m0 + lrow + 32) * 512 + lcol);
        rb0 = *(const uint4*)(sB + (size_t)(n0 + lrow) * 512 + lcol);
        rb1 = *(const uint4*)(sB + (size_t)(n0 + lrow + 32) * 512 + lcol);
    }

#pragma unroll 1
    for (int t = 0; t < 24; t++) {
        __syncthreads();
        *(uint4*)(As + lrow * GSTRIDE + lcol) = ra0;
        *(uint4*)(As + (lrow + 32) * GSTRIDE + lcol) = ra1;
        *(uint4*)(Bs + lrow * GSTRIDE + lcol) = rb0;
        *(uint4*)(Bs + (lrow + 32) * GSTRIDE + lcol) = rb1;
        __syncthreads();

        if (t < 23) {
            const int tn = t + 1;
            const int p = tn >> 3;              // 0 hi*hi, 1 lo*hi, 2 hi*lo
            const int kreal = (tn & 7) * 64;
            const __nv_bfloat16* sA = (p == 1) ? g_Alo : g_Ahi;
            const __nv_bfloat16* sB = (p == 2) ? g_Wtlo : g_Wthi;
            ra0 = *(const uint4*)(sA + (size_t)(m0 + lrow) * 512 + kreal + lcol);
            ra1 = *(const uint4*)(sA + (size_t)(m0 + lrow + 32) * 512 + kreal + lcol);
            rb0 = *(const uint4*)(sB + (size_t)(n0 + lrow) * 512 + kreal + lcol);
            rb1 = *(const uint4*)(sB + (size_t)(n0 + lrow + 32) * 512 + kreal + lcol);
        }

#pragma unroll
        for (int kk = 0; kk < 64; kk += 16) {
            unsigned int a0, a1, a2, a3;
            a0 = *(const unsigned int*)(As + (wm + r) * GSTRIDE + kk + c);
            a1 = *(const unsigned int*)(As + (wm + r + 8) * GSTRIDE + kk + c);
            a2 = *(const unsigned int*)(As + (wm + r) * GSTRIDE + kk + c + 8);
            a3 = *(const unsigned int*)(As + (wm + r + 8) * GSTRIDE + kk + c + 8);
#pragma unroll
            for (int j = 0; j < 4; j++) {
                const int n = wn + j * 8 + r;
                unsigned int b0 = *(const unsigned int*)(Bs + n * GSTRIDE + kk + c);
                unsigned int b1 = *(const unsigned int*)(Bs + n * GSTRIDE + kk + c + 8);
                asm volatile(
                    "mma.sync.aligned.m16n8k16.row.col.f32.bf16.bf16.f32 "
                    "{%0,%1,%2,%3}, {%4,%5,%6,%7}, {%8,%9}, {%0,%1,%2,%3};"
                    : "+f"(acc[j][0]), "+f"(acc[j][1]),
                      "+f"(acc[j][2]), "+f"(acc[j][3])
                    : "r"(a0), "r"(a1), "r"(a2), "r"(a3), "r"(b0), "r"(b1));
            }
        }
    }

    float* C = (float*)g_P;
    const int n2 = (lane & 3) * 2;
#pragma unroll
    for (int j = 0; j < 4; j++) {
        const int col = n0 + wn + j * 8 + n2;
        float* base = C + (size_t)(m0 + wm + r) * 512 + col;
        *(float2*)base = make_float2(acc[j][0], acc[j][1]);
        *(float2*)(base + 8 * 512) = make_float2(acc[j][2], acc[j][3]);
    }
}

// ---------------------------------------------------------------------------
// Kernel 3: combine.  out[b,s,h] = P[s,h] + N[nest,h] + G[seg,h]
// One thread per (s,h4); loops over ALL 64 batches -> P read exactly once.
// Streaming stores keep the 256 MB of dead output lines out of L2's way.
// ---------------------------------------------------------------------------
__global__ void __launch_bounds__(256)
combine_kernel(float4* __restrict__ out) {
    const unsigned int j = blockIdx.x * 256u + threadIdx.x;  // < 262144
    const int h4 = j & 127;
    const int s = j >> 7;            // 0..2047

    const float4 p = g_P[s * H4 + h4];
    const unsigned char* combo = g_combo + s;
#pragma unroll 8
    for (int b = 0; b < BB; b++) {
        const unsigned char c = combo[b * SS];
        const float4 n = g_N[(c >> 3) * H4 + h4];
        const float4 g = g_G[(c & 7) * H4 + h4];
        float4 o;
        o.x = p.x + n.x + g.x;
        o.y = p.y + n.y + g.y;
        o.z = p.z + n.z + g.z;
        o.w = p.w + n.w + g.w;
        __stcs(&out[(((unsigned)b * SS + s) << 7) + h4], o);
    }
}

// ---------------------------------------------------------------------------
extern "C" void kernel_launch(void* const* d_in, const int* in_sizes, int n_in,
                              void* d_out, int out_size) {
    const int*   tok  = (const int*)d_in[0];    // token_ids [64,2048] int32
    const float* pos  = (const float*)d_in[1];  // pos_table [2048,512]
    const float* nest = (const float*)d_in[2];  // nest_table [16,512]
    const float* seg  = (const float*)d_in[3];  // seg_table [8,512]
    const float* W    = (const float*)d_in[4];  // W [1536,512]
    float4* out = (float4*)d_out;               // [64,2048,512] f32

    prep_kernel<<<416, 256>>>(tok, pos, nest, seg, W);
    gemm_pos_mma<<<256, 256>>>();
    combine_kernel<<<SS * H4 / 256, 256>>>(out);
}

// round 7
// speedup vs baseline: 2.5051x; 1.0636x over previous
#include <cuda_runtime.h>
#include <cuda_bf16.h>

// Problem constants
#define BB 64
#define SS 2048
#define HH 512

// Scratch (module-scope device globals; no runtime allocation)
__device__ float g_N[16 * HH];              // nest_table @ W[512:1024]
__device__ float g_G[8 * HH];               // seg_table  @ W[1024:1536]
__device__ unsigned char g_combo[BB * SS];  // (nest<<3)|seg per token
__device__ __nv_bfloat16 g_Wthi[HH * HH];   // W[0:512]^T hi (n-major, k contig)
__device__ __nv_bfloat16 g_Wtlo[HH * HH];   // W[0:512]^T lo

// ---------------------------------------------------------------------------
// Small-GEMM body: one CTA = (8 table rows) x (32-col chunk).
// 256 threads = 32 cols x 8 k-eighths; thread accumulates 8 rows.
// ---------------------------------------------------------------------------
__device__ __forceinline__ void small_gemm_body(
    const float* __restrict__ a, const float* __restrict__ Wp,
    float* __restrict__ outp, int colbase, float* sbuf, int tid) {
    float* arow = sbuf;                       // 8*512 floats
    for (int i = tid; i < 8 * 512; i += 256) arow[i] = a[i];
    __syncthreads();

    const int c = tid & 31;
    const int kg = tid >> 5;                  // 0..7
    const int col = colbase + c;
    const float* wptr = Wp + (size_t)(kg * 64) * 512 + col;
    const float* ar = arow + kg * 64;

    float acc[8];
#pragma unroll
    for (int r = 0; r < 8; r++) acc[r] = 0.f;

#pragma unroll 1
    for (int kk = 0; kk < 64; kk += 8) {
        float w[8];
#pragma unroll
        for (int u = 0; u < 8; u++) w[u] = wptr[(size_t)(kk + u) * 512];
#pragma unroll
        for (int u = 0; u < 8; u++)
#pragma unroll
            for (int r = 0; r < 8; r++)
                acc[r] += ar[r * 512 + kk + u] * w[u];
    }

    __syncthreads();
    float* red = sbuf;                        // 8*8*32 floats
#pragma unroll
    for (int r = 0; r < 8; r++)
        red[(kg * 8 + r) * 32 + c] = acc[r];
    __syncthreads();

    if (tid < 256) {
        const int r = tid >> 5, cc = tid & 31;
        if (r < 8) {
            float s = 0.f;
#pragma unroll
            for (int g = 0; g < 8; g++) s += red[(g * 8 + r) * 32 + cc];
            outp[r * 512 + colbase + cc] = s;
        }
    }
}

// ---------------------------------------------------------------------------
// Kernel 1 "prep": 176 blocks x 256 threads.
//   [0,48):    small-table GEMMs (N: 16 chunks x 2 row-halves, G: 16 chunks)
//   [48,112):  W split+transpose via smem tile
//   [112,176): syntax scan, warp-shuffle Lindley prefix
// ---------------------------------------------------------------------------
__global__ void __launch_bounds__(256)
prep_kernel(const int* __restrict__ tok,
            const float* __restrict__ nest,
            const float* __restrict__ seg,
            const float* __restrict__ W) {
    __shared__ float sbuf[4160];              // 16.6 KB
    const int bid = blockIdx.x;
    const int tid = threadIdx.x;

    if (bid < 48) {
        // ---- small GEMMs ----
        if (bid < 32) {                       // N table, 2 row halves
            const int rh = bid >> 4;          // 0/1
            const int colbase = (bid & 15) * 32;
            small_gemm_body(nest + rh * 8 * 512, W + 512 * 512,
                            g_N + rh * 8 * 512, colbase, sbuf, tid);
        } else {                              // G table
            const int colbase = (bid - 32) * 32;
            small_gemm_body(seg, W + 1024 * 512, g_G, colbase, sbuf, tid);
        }
    } else if (bid < 112) {
        // ---- W[0:512] split + transpose: 8x8 tiles of 64x64 ----
        const int tb = bid - 48;
        const int ki = tb >> 3, ni = tb & 7;
        float* St = sbuf;                     // 64 x 65
#pragma unroll
        for (int l = 0; l < 4; l++) {
            const int idx = tid + l * 256;
            const int kr = idx >> 4;
            const int c4 = idx & 15;
            float4 v = *(const float4*)(W + (size_t)(ki * 64 + kr) * 512 + ni * 64 + c4 * 4);
            St[kr * 65 + c4 * 4 + 0] = v.x;
            St[kr * 65 + c4 * 4 + 1] = v.y;
            St[kr * 65 + c4 * 4 + 2] = v.z;
            St[kr * 65 + c4 * 4 + 3] = v.w;
        }
        __syncthreads();

        const int n = tid >> 2;               // 0..63
        const int kg = tid & 3;               // 16-k group
        __align__(16) __nv_bfloat162 hiu[8];
        __align__(16) __nv_bfloat162 lou[8];
#pragma unroll
        for (int e = 0; e < 16; e += 2) {
            float f0 = St[(kg * 16 + e) * 65 + n];
            float f1 = St[(kg * 16 + e + 1) * 65 + n];
            __nv_bfloat16 h0 = __float2bfloat16_rn(f0);
            __nv_bfloat16 h1 = __float2bfloat16_rn(f1);
            __nv_bfloat16 l0 = __float2bfloat16_rn(f0 - __bfloat162float(h0));
            __nv_bfloat16 l1 = __float2bfloat16_rn(f1 - __bfloat162float(h1));
            hiu[e >> 1] = __nv_bfloat162(h0, h1);
            lou[e >> 1] = __nv_bfloat162(l0, l1);
        }
        const size_t off = (size_t)(ni * 64 + n) * 512 + ki * 64 + kg * 16;
        *(uint4*)(g_Wthi + off) = ((uint4*)hiu)[0];
        *(uint4*)(g_Wthi + off + 8) = ((uint4*)hiu)[1];
        *(uint4*)(g_Wtlo + off) = ((uint4*)lou)[0];
        *(uint4*)(g_Wtlo + off + 8) = ((uint4*)lou)[1];
    } else {
        // ---- syntax scan with warp-shuffle parallel prefix ----
        int* sh_tok = (int*)sbuf;             // 2048 ints
        int* wsum = (int*)sbuf + 2048;
        int* wmin = wsum + 8;
        int* wcnt = wmin + 8;

        const int b = bid - 112;
        const int* t = tok + b * SS;
        for (int i = tid; i < SS; i += 256) sh_tok[i] = t[i];
        __syncthreads();

        const int base = tid * 8;
        int s = 0, mn = 0, cnt = 0;
#pragma unroll
        for (int e = 0; e < 8; e++) {
            int tk = sh_tok[base + e];
            int op = (tk == 40) | (tk == 123) | (tk == 91);
            int cl = (tk == 41) | (tk == 125) | (tk == 93);
            s += op - cl;
            mn = min(mn, s);
            cnt += (tk > 39990);
        }

        const int lane = tid & 31;
        const int wid = tid >> 5;
        int Si = s, Mi = mn, Ci = cnt;
#pragma unroll
        for (int d = 1; d < 32; d <<= 1) {
            int So = __shfl_up_sync(0xffffffffu, Si, d);
            int Mo = __shfl_up_sync(0xffffffffu, Mi, d);
            int Co = __shfl_up_sync(0xffffffffu, Ci, d);
            if (lane >= d) { Mi = min(Mo, So + Mi); Si = So + Si; Ci = Co + Ci; }
        }
        if (lane == 31) { wsum[wid] = Si; wmin[wid] = Mi; wcnt[wid] = Ci; }

        int Se = __shfl_up_sync(0xffffffffu, Si, 1);
        int Me = __shfl_up_sync(0xffffffffu, Mi, 1);
        int Ce = __shfl_up_sync(0xffffffffu, Ci, 1);
        if (lane == 0) { Se = 0; Me = 0; Ce = 0; }
        __syncthreads();

        int Sw = 0, Mw = 0, Cw = 0;
        for (int w = 0; w < wid; w++) {
            Mw = min(Mw, Sw + wmin[w]);
            Sw += wsum[w];
            Cw += wcnt[w];
        }
        int S_pre = Sw + Se;
        int M_pre = min(Mw, Sw + Me);
        int C_pre = Cw + Ce;

        s = S_pre; mn = M_pre; cnt = C_pre;
        unsigned char* out = g_combo + b * SS + base;
#pragma unroll
        for (int e = 0; e < 8; e++) {
            int tk = sh_tok[base + e];
            int op = (tk == 40) | (tk == 123) | (tk == 91);
            int cl = (tk == 41) | (tk == 125) | (tk == 93);
            s += op - cl;
            mn = min(mn, s);
            cnt += (tk > 39990);
            int lvl = min(s - mn, 15);
            out[e] = (unsigned char)((lvl << 3) | (cnt & 7));
        }
    }
}

// ---------------------------------------------------------------------------
// Kernel 2 "mega": fused GEMM + combine. 256 CTAs, 256 threads.
// Phase 1: P-tile = A(f32, split in-register) @ Wt(hi/lo bf16), 3-term
//          split-precision mma, acc in regs (never written to gmem).
// Phase 2: build NG[c][h]=N[c>>3][h]+G[c&7][h] slice + combo slice in smem,
//          stream out all 64 batches of the tile with __stcs.
// ---------------------------------------------------------------------------
#define GSTRIDE 72        // padded smem row stride (bf16)
#define NGS 66            // NG row stride (floats)
// smem layout (bytes):
//   mma:  As_hi [0,9216) As_lo [9216,18432) Bs_hi [18432,27648) Bs_lo [27648,36864)
//   epi:  NG [0,33792=128*66*4) sc [33792,37888) Ns [37888,41984) Gs [41984,44032)
__global__ void __launch_bounds__(256)
mega_kernel(const float* __restrict__ A, float* __restrict__ out) {
    __shared__ __align__(16) char smem_raw[44032];
    __nv_bfloat16* As_hi = (__nv_bfloat16*)smem_raw;
    __nv_bfloat16* As_lo = (__nv_bfloat16*)(smem_raw + 9216);
    __nv_bfloat16* Bs_hi = (__nv_bfloat16*)(smem_raw + 18432);
    __nv_bfloat16* Bs_lo = (__nv_bfloat16*)(smem_raw + 27648);

    const int tid = threadIdx.x;
    const int q = blockIdx.x;
    const int m0 = (q & 31) * 64;        // s range
    const int n0 = (q >> 5) * 64;        // h range

    const int wid = tid >> 5;
    const int lane = tid & 31;
    const int wm = (wid & 3) * 16;
    const int wn = (wid >> 2) * 32;

    // B-tile load coords (uint4 = 8 bf16 along k)
    const int lrow = tid >> 3;           // 0..31 (+32)
    const int lcol = (tid & 7) * 8;

    float acc[4][4];
#pragma unroll
    for (int j = 0; j < 4; j++)
#pragma unroll
        for (int p = 0; p < 4; p++) acc[j][p] = 0.f;

    const int r = lane >> 2;
    const int c = (lane & 3) * 2;
    const int n2 = (lane & 3) * 2;

    // prefetch registers
    float4 fa[4];
    uint4 wh0, wh1, wl0, wl1;
    {
#pragma unroll
        for (int l = 0; l < 4; l++) {
            const int idx = tid + l * 256;
            fa[l] = *(const float4*)(A + (size_t)(m0 + (idx >> 4)) * 512 + (idx & 15) * 4);
        }
        wh0 = *(const uint4*)(g_Wthi + (size_t)(n0 + lrow) * 512 + lcol);
        wh1 = *(const uint4*)(g_Wthi + (size_t)(n0 + lrow + 32) * 512 + lcol);
        wl0 = *(const uint4*)(g_Wtlo + (size_t)(n0 + lrow) * 512 + lcol);
        wl1 = *(const uint4*)(g_Wtlo + (size_t)(n0 + lrow + 32) * 512 + lcol);
    }

#pragma unroll 1
    for (int t = 0; t < 8; t++) {
        __syncthreads();
        // stage A (convert f32 -> hi/lo bf16) and W tiles
#pragma unroll
        for (int l = 0; l < 4; l++) {
            const int idx = tid + l * 256;
            const int arow = idx >> 4;
            const int ac = (idx & 15) * 4;
            float4 v = fa[l];
            __nv_bfloat16 hx = __float2bfloat16_rn(v.x);
            __nv_bfloat16 hy = __float2bfloat16_rn(v.y);
            __nv_bfloat16 hz = __float2bfloat16_rn(v.z);
            __nv_bfloat16 hw = __float2bfloat16_rn(v.w);
            *(__nv_bfloat162*)(As_hi + arow * GSTRIDE + ac) = __nv_bfloat162(hx, hy);
            *(__nv_bfloat162*)(As_hi + arow * GSTRIDE + ac + 2) = __nv_bfloat162(hz, hw);
            __nv_bfloat16 lx = __float2bfloat16_rn(v.x - __bfloat162float(hx));
            __nv_bfloat16 ly = __float2bfloat16_rn(v.y - __bfloat162float(hy));
            __nv_bfloat16 lz = __float2bfloat16_rn(v.z - __bfloat162float(hz));
            __nv_bfloat16 lw = __float2bfloat16_rn(v.w - __bfloat162float(hw));
            *(__nv_bfloat162*)(As_lo + arow * GSTRIDE + ac) = __nv_bfloat162(lx, ly);
            *(__nv_bfloat162*)(As_lo + arow * GSTRIDE + ac + 2) = __nv_bfloat162(lz, lw);
        }
        *(uint4*)(Bs_hi + lrow * GSTRIDE + lcol) = wh0;
        *(uint4*)(Bs_hi + (lrow + 32) * GSTRIDE + lcol) = wh1;
        *(uint4*)(Bs_lo + lrow * GSTRIDE + lcol) = wl0;
        *(uint4*)(Bs_lo + (lrow + 32) * GSTRIDE + lcol) = wl1;
        __syncthreads();

        if (t < 7) {
            const int k0 = (t + 1) * 64;
#pragma unroll
            for (int l = 0; l < 4; l++) {
                const int idx = tid + l * 256;
                fa[l] = *(const float4*)(A + (size_t)(m0 + (idx >> 4)) * 512 + k0 + (idx & 15) * 4);
            }
            wh0 = *(const uint4*)(g_Wthi + (size_t)(n0 + lrow) * 512 + k0 + lcol);
            wh1 = *(const uint4*)(g_Wthi + (size_t)(n0 + lrow + 32) * 512 + k0 + lcol);
            wl0 = *(const uint4*)(g_Wtlo + (size_t)(n0 + lrow) * 512 + k0 + lcol);
            wl1 = *(const uint4*)(g_Wtlo + (size_t)(n0 + lrow + 32) * 512 + k0 + lcol);
        }

#pragma unroll
        for (int kk = 0; kk < 64; kk += 16) {
            unsigned int ah0, ah1, ah2, ah3, al0, al1, al2, al3;
            ah0 = *(const unsigned int*)(As_hi + (wm + r) * GSTRIDE + kk + c);
            ah1 = *(const unsigned int*)(As_hi + (wm + r + 8) * GSTRIDE + kk + c);
            ah2 = *(const unsigned int*)(As_hi + (wm + r) * GSTRIDE + kk + c + 8);
            ah3 = *(const unsigned int*)(As_hi + (wm + r + 8) * GSTRIDE + kk + c + 8);
            al0 = *(const unsigned int*)(As_lo + (wm + r) * GSTRIDE + kk + c);
            al1 = *(const unsigned int*)(As_lo + (wm + r + 8) * GSTRIDE + kk + c);
            al2 = *(const unsigned int*)(As_lo + (wm + r) * GSTRIDE + kk + c + 8);
            al3 = *(const unsigned int*)(As_lo + (wm + r + 8) * GSTRIDE + kk + c + 8);
#pragma unroll
            for (int j = 0; j < 4; j++) {
                const int n = wn + j * 8 + r;
                unsigned int bh0 = *(const unsigned int*)(Bs_hi + n * GSTRIDE + kk + c);
                unsigned int bh1 = *(const unsigned int*)(Bs_hi + n * GSTRIDE + kk + c + 8);
                unsigned int bl0 = *(const unsigned int*)(Bs_lo + n * GSTRIDE + kk + c);
                unsigned int bl1 = *(const unsigned int*)(Bs_lo + n * GSTRIDE + kk + c + 8);
                asm volatile(
                    "mma.sync.aligned.m16n8k16.row.col.f32.bf16.bf16.f32 "
                    "{%0,%1,%2,%3}, {%4,%5,%6,%7}, {%8,%9}, {%0,%1,%2,%3};"
                    : "+f"(acc[j][0]), "+f"(acc[j][1]), "+f"(acc[j][2]), "+f"(acc[j][3])
                    : "r"(ah0), "r"(ah1), "r"(ah2), "r"(ah3), "r"(bh0), "r"(bh1));
                asm volatile(
                    "mma.sync.aligned.m16n8k16.row.col.f32.bf16.bf16.f32 "
                    "{%0,%1,%2,%3}, {%4,%5,%6,%7}, {%8,%9}, {%0,%1,%2,%3};"
                    : "+f"(acc[j][0]), "+f"(acc[j][1]), "+f"(acc[j][2]), "+f"(acc[j][3])
                    : "r"(al0), "r"(al1), "r"(al2), "r"(al3), "r"(bh0), "r"(bh1));
                asm volatile(
                    "mma.sync.aligned.m16n8k16.row.col.f32.bf16.bf16.f32 "
                    "{%0,%1,%2,%3}, {%4,%5,%6,%7}, {%8,%9}, {%0,%1,%2,%3};"
                    : "+f"(acc[j][0]), "+f"(acc[j][1]), "+f"(acc[j][2]), "+f"(acc[j][3])
                    : "r"(ah0), "r"(ah1), "r"(ah2), "r"(ah3), "r"(bl0), "r"(bl1));
            }
        }
    }

    // ---------------- epilogue: fused combine ----------------
    __syncthreads();    // mma smem reads done; reuse smem

    float* NG = (float*)smem_raw;                              // 128 x NGS
    unsigned char* sc = (unsigned char*)(smem_raw + 33792);    // 64 b x 64 rows
    float* Ns = (float*)(smem_raw + 37888);                    // 16 x 64
    float* Gs = (float*)(smem_raw + 41984);                    // 8 x 64

    // stage N/G slices + combo
#pragma unroll
    for (int l = 0; l < 4; l++) {
        const int i = tid + l * 256;                           // 0..1023
        Ns[i] = g_N[(i >> 6) * 512 + n0 + (i & 63)];
    }
#pragma unroll
    for (int l = 0; l < 2; l++) {
        const int i = tid + l * 256;                           // 0..511
        Gs[i] = g_G[(i >> 6) * 512 + n0 + (i & 63)];
    }
    {
        const int b = tid >> 2;
        const int part = tid & 3;
        *(uint4*)(sc + b * 64 + part * 16) =
            *(const uint4*)(g_combo + b * SS + m0 + part * 16);
    }
    __syncthreads();

    // build NG
#pragma unroll
    for (int l = 0; l < 32; l++) {
        const int i = tid + l * 256;                           // 0..8191
        const int cc = i >> 6;
        const int col = i & 63;
        NG[cc * NGS + col] = Ns[(cc >> 3) * 64 + col] + Gs[(cc & 7) * 64 + col];
    }
    __syncthreads();

    // stream all 64 batches of this tile
    const int row0 = wm + r;                 // local row (and +8)
    float2* out2 = (float2*)out;
#pragma unroll 4
    for (int b = 0; b < BB; b++) {
        const int c0 = sc[b * 64 + row0];
        const int c1 = sc[b * 64 + row0 + 8];
        const float* ng0 = NG + c0 * NGS;
        const float* ng1 = NG + c1 * NGS;
        const size_t base0 = ((size_t)b * SS + m0 + row0) * 256 + (n0 >> 1);
        const size_t base1 = base0 + 8 * 256;
#pragma unroll
        for (int j = 0; j < 4; j++) {
            const int coll = wn + j * 8 + n2;
            float2 e0 = *(const float2*)(ng0 + coll);
            float2 e1 = *(const float2*)(ng1 + coll);
            __stcs(out2 + base0 + (coll >> 1),
                   make_float2(acc[j][0] + e0.x, acc[j][1] + e0.y));
            __stcs(out2 + base1 + (coll >> 1),
                   make_float2(acc[j][2] + e1.x, acc[j][3] + e1.y));
        }
    }
}

// ---------------------------------------------------------------------------
extern "C" void kernel_launch(void* const* d_in, const int* in_sizes, int n_in,
                              void* d_out, int out_size) {
    const int*   tok  = (const int*)d_in[0];    // token_ids [64,2048] int32
    const float* pos  = (const float*)d_in[1];  // pos_table [2048,512]
    const float* nest = (const float*)d_in[2];  // nest_table [16,512]
    const float* seg  = (const float*)d_in[3];  // seg_table [8,512]
    const float* W    = (const float*)d_in[4];  // W [1536,512]
    float* out = (float*)d_out;                 // [64,2048,512] f32

    prep_kernel<<<176, 256>>>(tok, nest, seg, W);
    mega_kernel<<<256, 256>>>(pos, out);
}

// round 8
// speedup vs baseline: 2.6376x; 1.0529x over previous
#include <cuda_runtime.h>
#include <cuda_bf16.h>

// Problem constants
#define BB 64
#define SS 2048
#define HH 512

// Scratch (module-scope device globals; no runtime allocation)
__device__ float g_N[16 * HH];              // nest_table @ W[512:1024]
__device__ float g_G[8 * HH];               // seg_table  @ W[1024:1536]
__device__ unsigned char g_combo[BB * SS];  // (nest<<3)|seg per token
__device__ __nv_bfloat16 g_Wthi[HH * HH];   // W[0:512]^T hi (n-major, k contig)
__device__ __nv_bfloat16 g_Wtlo[HH * HH];   // W[0:512]^T lo

// ---------------------------------------------------------------------------
// Small-GEMM body: one CTA = (8 table rows) x (32-col chunk).
// ---------------------------------------------------------------------------
__device__ __forceinline__ void small_gemm_body(
    const float* __restrict__ a, const float* __restrict__ Wp,
    float* __restrict__ outp, int colbase, float* sbuf, int tid) {
    float* arow = sbuf;                       // 8*512 floats
    for (int i = tid; i < 8 * 512; i += 256) arow[i] = a[i];
    __syncthreads();

    const int c = tid & 31;
    const int kg = tid >> 5;                  // 0..7
    const int col = colbase + c;
    const float* wptr = Wp + (size_t)(kg * 64) * 512 + col;
    const float* ar = arow + kg * 64;

    float acc[8];
#pragma unroll
    for (int r = 0; r < 8; r++) acc[r] = 0.f;

#pragma unroll 1
    for (int kk = 0; kk < 64; kk += 8) {
        float w[8];
#pragma unroll
        for (int u = 0; u < 8; u++) w[u] = wptr[(size_t)(kk + u) * 512];
#pragma unroll
        for (int u = 0; u < 8; u++)
#pragma unroll
            for (int r = 0; r < 8; r++)
                acc[r] += ar[r * 512 + kk + u] * w[u];
    }

    __syncthreads();
    float* red = sbuf;                        // 8*8*32 floats
#pragma unroll
    for (int r = 0; r < 8; r++)
        red[(kg * 8 + r) * 32 + c] = acc[r];
    __syncthreads();

    {
        const int r = tid >> 5, cc = tid & 31;
        if (r < 8) {
            float s = 0.f;
#pragma unroll
            for (int g = 0; g < 8; g++) s += red[(g * 8 + r) * 32 + cc];
            outp[r * 512 + colbase + cc] = s;
        }
    }
}

// ---------------------------------------------------------------------------
// Kernel 1 "prep": 176 blocks x 256 threads.
//   [0,48):    small-table GEMMs   [48,112): W split+transpose
//   [112,176): syntax scan (warp-shuffle Lindley prefix)
// ---------------------------------------------------------------------------
__global__ void __launch_bounds__(256)
prep_kernel(const int* __restrict__ tok,
            const float* __restrict__ nest,
            const float* __restrict__ seg,
            const float* __restrict__ W) {
    __shared__ float sbuf[4160];              // 16.6 KB
    const int bid = blockIdx.x;
    const int tid = threadIdx.x;

    if (bid < 48) {
        if (bid < 32) {                       // N table, 2 row halves
            const int rh = bid >> 4;
            const int colbase = (bid & 15) * 32;
            small_gemm_body(nest + rh * 8 * 512, W + 512 * 512,
                            g_N + rh * 8 * 512, colbase, sbuf, tid);
        } else {                              // G table
            const int colbase = (bid - 32) * 32;
            small_gemm_body(seg, W + 1024 * 512, g_G, colbase, sbuf, tid);
        }
    } else if (bid < 112) {
        // ---- W[0:512] split + transpose: 8x8 tiles of 64x64 ----
        const int tb = bid - 48;
        const int ki = tb >> 3, ni = tb & 7;
        float* St = sbuf;                     // 64 x 65
#pragma unroll
        for (int l = 0; l < 4; l++) {
            const int idx = tid + l * 256;
            const int kr = idx >> 4;
            const int c4 = idx & 15;
            float4 v = *(const float4*)(W + (size_t)(ki * 64 + kr) * 512 + ni * 64 + c4 * 4);
            St[kr * 65 + c4 * 4 + 0] = v.x;
            St[kr * 65 + c4 * 4 + 1] = v.y;
            St[kr * 65 + c4 * 4 + 2] = v.z;
            St[kr * 65 + c4 * 4 + 3] = v.w;
        }
        __syncthreads();

        const int n = tid >> 2;
        const int kg = tid & 3;
        __align__(16) __nv_bfloat162 hiu[8];
        __align__(16) __nv_bfloat162 lou[8];
#pragma unroll
        for (int e = 0; e < 16; e += 2) {
            float f0 = St[(kg * 16 + e) * 65 + n];
            float f1 = St[(kg * 16 + e + 1) * 65 + n];
            __nv_bfloat16 h0 = __float2bfloat16_rn(f0);
            __nv_bfloat16 h1 = __float2bfloat16_rn(f1);
            __nv_bfloat16 l0 = __float2bfloat16_rn(f0 - __bfloat162float(h0));
            __nv_bfloat16 l1 = __float2bfloat16_rn(f1 - __bfloat162float(h1));
            hiu[e >> 1] = __nv_bfloat162(h0, h1);
            lou[e >> 1] = __nv_bfloat162(l0, l1);
        }
        const size_t off = (size_t)(ni * 64 + n) * 512 + ki * 64 + kg * 16;
        *(uint4*)(g_Wthi + off) = ((uint4*)hiu)[0];
        *(uint4*)(g_Wthi + off + 8) = ((uint4*)hiu)[1];
        *(uint4*)(g_Wtlo + off) = ((uint4*)lou)[0];
        *(uint4*)(g_Wtlo + off + 8) = ((uint4*)lou)[1];
    } else {
        // ---- syntax scan with warp-shuffle parallel prefix ----
        int* sh_tok = (int*)sbuf;
        int* wsum = (int*)sbuf + 2048;
        int* wmin = wsum + 8;
        int* wcnt = wmin + 8;

        const int b = bid - 112;
        const int* t = tok + b * SS;
        for (int i = tid; i < SS; i += 256) sh_tok[i] = t[i];
        __syncthreads();

        const int base = tid * 8;
        int s = 0, mn = 0, cnt = 0;
#pragma unroll
        for (int e = 0; e < 8; e++) {
            int tk = sh_tok[base + e];
            int op = (tk == 40) | (tk == 123) | (tk == 91);
            int cl = (tk == 41) | (tk == 125) | (tk == 93);
            s += op - cl;
            mn = min(mn, s);
            cnt += (tk > 39990);
        }

        const int lane = tid & 31;
        const int wid = tid >> 5;
        int Si = s, Mi = mn, Ci = cnt;
#pragma unroll
        for (int d = 1; d < 32; d <<= 1) {
            int So = __shfl_up_sync(0xffffffffu, Si, d);
            int Mo = __shfl_up_sync(0xffffffffu, Mi, d);
            int Co = __shfl_up_sync(0xffffffffu, Ci, d);
            if (lane >= d) { Mi = min(Mo, So + Mi); Si = So + Si; Ci = Co + Ci; }
        }
        if (lane == 31) { wsum[wid] = Si; wmin[wid] = Mi; wcnt[wid] = Ci; }

        int Se = __shfl_up_sync(0xffffffffu, Si, 1);
        int Me = __shfl_up_sync(0xffffffffu, Mi, 1);
        int Ce = __shfl_up_sync(0xffffffffu, Ci, 1);
        if (lane == 0) { Se = 0; Me = 0; Ce = 0; }
        __syncthreads();

        int Sw = 0, Mw = 0, Cw = 0;
        for (int w = 0; w < wid; w++) {
            Mw = min(Mw, Sw + wmin[w]);
            Sw += wsum[w];
            Cw += wcnt[w];
        }
        int S_pre = Sw + Se;
        int M_pre = min(Mw, Sw + Me);
        int C_pre = Cw + Ce;

        s = S_pre; mn = M_pre; cnt = C_pre;
        unsigned char* out = g_combo + b * SS + base;
#pragma unroll
        for (int e = 0; e < 8; e++) {
            int tk = sh_tok[base + e];
            int op = (tk == 40) | (tk == 123) | (tk == 91);
            int cl = (tk == 41) | (tk == 125) | (tk == 93);
            s += op - cl;
            mn = min(mn, s);
            cnt += (tk > 39990);
            int lvl = min(s - mn, 15);
            out[e] = (unsigned char)((lvl << 3) | (cnt & 7));
        }
    }
}

// ---------------------------------------------------------------------------
// Kernel 2 "mega": fused GEMM + combine. 128 CTAs x 2 m-tiles each (perfect
// wave balance). Epilogue: acc tile staged to smem once, hoisted to regs,
// then per-batch table add + STG.128 streaming stores.
// ---------------------------------------------------------------------------
#define GSTRIDE 72        // padded smem row stride (bf16)
// smem union (36864 B):
//   mma:  As_hi [0,9216) As_lo [9216,18432) Bs_hi [18432,27648) Bs_lo [27648,36864)
//   epi:  tileS [0,16384) Ns [16384,20480) Gs [20480,22528) sc [22528,26624)
__global__ void __launch_bounds__(256)
mega_kernel(const float* __restrict__ A, float* __restrict__ out) {
    __shared__ __align__(16) char smem_raw[36864];
    __nv_bfloat16* As_hi = (__nv_bfloat16*)smem_raw;
    __nv_bfloat16* As_lo = (__nv_bfloat16*)(smem_raw + 9216);
    __nv_bfloat16* Bs_hi = (__nv_bfloat16*)(smem_raw + 18432);
    __nv_bfloat16* Bs_lo = (__nv_bfloat16*)(smem_raw + 27648);

    const int tid = threadIdx.x;
    const int q = blockIdx.x;            // 0..127
    const int n0 = (q >> 4) * 64;        // h band
    const int mi = q & 15;               // m pair index

    const int wid = tid >> 5;
    const int lane = tid & 31;
    const int wm = (wid & 3) * 16;
    const int wn = (wid >> 2) * 32;

    const int lrow = tid >> 3;
    const int lcol = (tid & 7) * 8;

    const int r = lane >> 2;
    const int c = (lane & 3) * 2;
    const int n2 = (lane & 3) * 2;

#pragma unroll 1
    for (int t2 = 0; t2 < 2; t2++) {
        const int m0 = mi * 128 + t2 * 64;

        float acc[4][4];
#pragma unroll
        for (int j = 0; j < 4; j++)
#pragma unroll
            for (int p = 0; p < 4; p++) acc[j][p] = 0.f;

        // prefetch k-tile 0
        float4 fa[4];
        uint4 wh0, wh1, wl0, wl1;
#pragma unroll
        for (int l = 0; l < 4; l++) {
            const int idx = tid + l * 256;
            fa[l] = *(const float4*)(A + (size_t)(m0 + (idx >> 4)) * 512 + (idx & 15) * 4);
        }
        wh0 = *(const uint4*)(g_Wthi + (size_t)(n0 + lrow) * 512 + lcol);
        wh1 = *(const uint4*)(g_Wthi + (size_t)(n0 + lrow + 32) * 512 + lcol);
        wl0 = *(const uint4*)(g_Wtlo + (size_t)(n0 + lrow) * 512 + lcol);
        wl1 = *(const uint4*)(g_Wtlo + (size_t)(n0 + lrow + 32) * 512 + lcol);

#pragma unroll 1
        for (int t = 0; t < 8; t++) {
            __syncthreads();
            // stage A (split f32 -> hi/lo bf16 in-register) and W tiles
#pragma unroll
            for (int l = 0; l < 4; l++) {
                const int idx = tid + l * 256;
                const int arow = idx >> 4;
                const int ac = (idx & 15) * 4;
                float4 v = fa[l];
                __nv_bfloat16 hx = __float2bfloat16_rn(v.x);
                __nv_bfloat16 hy = __float2bfloat16_rn(v.y);
                __nv_bfloat16 hz = __float2bfloat16_rn(v.z);
                __nv_bfloat16 hw = __float2bfloat16_rn(v.w);
                *(__nv_bfloat162*)(As_hi + arow * GSTRIDE + ac) = __nv_bfloat162(hx, hy);
                *(__nv_bfloat162*)(As_hi + arow * GSTRIDE + ac + 2) = __nv_bfloat162(hz, hw);
                __nv_bfloat16 lx = __float2bfloat16_rn(v.x - __bfloat162float(hx));
                __nv_bfloat16 ly = __float2bfloat16_rn(v.y - __bfloat162float(hy));
                __nv_bfloat16 lz = __float2bfloat16_rn(v.z - __bfloat162float(hz));
                __nv_bfloat16 lw = __float2bfloat16_rn(v.w - __bfloat162float(hw));
                *(__nv_bfloat162*)(As_lo + arow * GSTRIDE + ac) = __nv_bfloat162(lx, ly);
                *(__nv_bfloat162*)(As_lo + arow * GSTRIDE + ac + 2) = __nv_bfloat162(lz, lw);
            }
            *(uint4*)(Bs_hi + lrow * GSTRIDE + lcol) = wh0;
            *(uint4*)(Bs_hi + (lrow + 32) * GSTRIDE + lcol) = wh1;
            *(uint4*)(Bs_lo + lrow * GSTRIDE + lcol) = wl0;
            *(uint4*)(Bs_lo + (lrow + 32) * GSTRIDE + lcol) = wl1;
            __syncthreads();

            if (t < 7) {
                const int k0 = (t + 1) * 64;
#pragma unroll
                for (int l = 0; l < 4; l++) {
                    const int idx = tid + l * 256;
                    fa[l] = *(const float4*)(A + (size_t)(m0 + (idx >> 4)) * 512 + k0 + (idx & 15) * 4);
                }
                wh0 = *(const uint4*)(g_Wthi + (size_t)(n0 + lrow) * 512 + k0 + lcol);
                wh1 = *(const uint4*)(g_Wthi + (size_t)(n0 + lrow + 32) * 512 + k0 + lcol);
                wl0 = *(const uint4*)(g_Wtlo + (size_t)(n0 + lrow) * 512 + k0 + lcol);
                wl1 = *(const uint4*)(g_Wtlo + (size_t)(n0 + lrow + 32) * 512 + k0 + lcol);
            }

#pragma unroll
            for (int kk = 0; kk < 64; kk += 16) {
                unsigned int ah0, ah1, ah2, ah3, al0, al1, al2, al3;
                ah0 = *(const unsigned int*)(As_hi + (wm + r) * GSTRIDE + kk + c);
                ah1 = *(const unsigned int*)(As_hi + (wm + r + 8) * GSTRIDE + kk + c);
                ah2 = *(const unsigned int*)(As_hi + (wm + r) * GSTRIDE + kk + c + 8);
                ah3 = *(const unsigned int*)(As_hi + (wm + r + 8) * GSTRIDE + kk + c + 8);
                al0 = *(const unsigned int*)(As_lo + (wm + r) * GSTRIDE + kk + c);
                al1 = *(const unsigned int*)(As_lo + (wm + r + 8) * GSTRIDE + kk + c);
                al2 = *(const unsigned int*)(As_lo + (wm + r) * GSTRIDE + kk + c + 8);
                al3 = *(const unsigned int*)(As_lo + (wm + r + 8) * GSTRIDE + kk + c + 8);
#pragma unroll
                for (int j = 0; j < 4; j++) {
                    const int n = wn + j * 8 + r;
                    unsigned int bh0 = *(const unsigned int*)(Bs_hi + n * GSTRIDE + kk + c);
                    unsigned int bh1 = *(const unsigned int*)(Bs_hi + n * GSTRIDE + kk + c + 8);
                    unsigned int bl0 = *(const unsigned int*)(Bs_lo + n * GSTRIDE + kk + c);
                    unsigned int bl1 = *(const unsigned int*)(Bs_lo + n * GSTRIDE + kk + c + 8);
                    asm volatile(
                        "mma.sync.aligned.m16n8k16.row.col.f32.bf16.bf16.f32 "
                        "{%0,%1,%2,%3}, {%4,%5,%6,%7}, {%8,%9}, {%0,%1,%2,%3};"
                        : "+f"(acc[j][0]), "+f"(acc[j][1]), "+f"(acc[j][2]), "+f"(acc[j][3])
                        : "r"(ah0), "r"(ah1), "r"(ah2), "r"(ah3), "r"(bh0), "r"(bh1));
                    asm volatile(
                        "mma.sync.aligned.m16n8k16.row.col.f32.bf16.bf16.f32 "
                        "{%0,%1,%2,%3}, {%4,%5,%6,%7}, {%8,%9}, {%0,%1,%2,%3};"
                        : "+f"(acc[j][0]), "+f"(acc[j][1]), "+f"(acc[j][2]), "+f"(acc[j][3])
                        : "r"(al0), "r"(al1), "r"(al2), "r"(al3), "r"(bh0), "r"(bh1));
                    asm volatile(
                        "mma.sync.aligned.m16n8k16.row.col.f32.bf16.bf16.f32 "
                        "{%0,%1,%2,%3}, {%4,%5,%6,%7}, {%8,%9}, {%0,%1,%2,%3};"
                        : "+f"(acc[j][0]), "+f"(acc[j][1]), "+f"(acc[j][2]), "+f"(acc[j][3])
                        : "r"(ah0), "r"(ah1), "r"(ah2), "r"(ah3), "r"(bl0), "r"(bl1));
                }
            }
        }

        // ---------------- epilogue ----------------
        __syncthreads();            // mma smem reads done; reuse smem

        float* tileS = (float*)smem_raw;                           // 64 x 64
        float* Ns = (float*)(smem_raw + 16384);                    // 16 x 64
        float* Gs = (float*)(smem_raw + 20480);                    // 8 x 64
        unsigned char* sc = (unsigned char*)(smem_raw + 22528);    // 64 x 64

        // stage acc tile
#pragma unroll
        for (int j = 0; j < 4; j++) {
            *(float2*)(tileS + (wm + r) * 64 + wn + j * 8 + n2) =
                make_float2(acc[j][0], acc[j][1]);
            *(float2*)(tileS + (wm + r + 8) * 64 + wn + j * 8 + n2) =
                make_float2(acc[j][2], acc[j][3]);
        }
        // stage table slices + combo
#pragma unroll
        for (int l = 0; l < 4; l++) {
            const int i = tid + l * 256;
            Ns[i] = g_N[(i >> 6) * 512 + n0 + (i & 63)];
        }
#pragma unroll
        for (int l = 0; l < 2; l++) {
            const int i = tid + l * 256;
            Gs[i] = g_G[(i >> 6) * 512 + n0 + (i & 63)];
        }
        {
            const int b = tid >> 2;
            const int part = tid & 3;
            *(uint4*)(sc + b * 64 + part * 16) =
                *(const uint4*)(g_combo + b * SS + m0 + part * 16);
        }
        __syncthreads();

        // re-partition: thread = (row = tid>>2) x 4 float4 cols
        const int row = tid >> 2;
        const int c4b = tid & 3;
        float4 tv[4];
#pragma unroll
        for (int k4 = 0; k4 < 4; k4++)
            tv[k4] = *(const float4*)(tileS + row * 64 + (c4b + k4 * 4) * 4);

        float4* out4 = (float4*)out;
        const unsigned rowbase = (m0 + row) * 128 + (n0 >> 2) + c4b;
#pragma unroll 2
        for (int b = 0; b < BB; b++) {
            const int cc = sc[b * 64 + row];
            const float* nrow = Ns + (cc >> 3) * 64;
            const float* grow = Gs + (cc & 7) * 64;
            const unsigned obase = b * (SS * 128u) + rowbase;
#pragma unroll
            for (int k4 = 0; k4 < 4; k4++) {
                const int col = (c4b + k4 * 4) * 4;
                float4 nv = *(const float4*)(nrow + col);
                float4 gv = *(const float4*)(grow + col);
                float4 o;
                o.x = tv[k4].x + nv.x + gv.x;
                o.y = tv[k4].y + nv.y + gv.y;
                o.z = tv[k4].z + nv.z + gv.z;
                o.w = tv[k4].w + nv.w + gv.w;
                __stcs(out4 + obase + k4 * 4, o);
            }
        }
        __syncthreads();            // epi smem reads done before next mma
    }
}

// ---------------------------------------------------------------------------
extern "C" void kernel_launch(void* const* d_in, const int* in_sizes, int n_in,
                              void* d_out, int out_size) {
    const int*   tok  = (const int*)d_in[0];    // token_ids [64,2048] int32
    const float* pos  = (const float*)d_in[1];  // pos_table [2048,512]
    const float* nest = (const float*)d_in[2];  // nest_table [16,512]
    const float* seg  = (const float*)d_in[3];  // seg_table [8,512]
    const float* W    = (const float*)d_in[4];  // W [1536,512]
    float* out = (float*)d_out;                 // [64,2048,512] f32

    prep_kernel<<<176, 256>>>(tok, nest, seg, W);
    mega_kernel<<<128, 256>>>(pos, out);
}

// round 9
// speedup vs baseline: 2.6651x; 1.0104x over previous
#include <cuda_runtime.h>
#include <cuda_bf16.h>

// Problem constants
#define BB 64
#define SS 2048
#define HH 512

// Scratch (module-scope device globals; no runtime allocation)
__device__ float g_N[16 * HH];              // nest_table @ W[512:1024]
__device__ float g_G[8 * HH];               // seg_table  @ W[1024:1536]
__device__ unsigned char g_combo[BB * SS];  // (nest<<3)|seg per token
__device__ __nv_bfloat16 g_Wthi[HH * HH];   // W[0:512]^T hi (n-major, k contig)
__device__ __nv_bfloat16 g_Wtlo[HH * HH];   // W[0:512]^T lo

// ---------------------------------------------------------------------------
// Small-GEMM body: one CTA = (8 table rows) x (32-col chunk).
// ---------------------------------------------------------------------------
__device__ __forceinline__ void small_gemm_body(
    const float* __restrict__ a, const float* __restrict__ Wp,
    float* __restrict__ outp, int colbase, float* sbuf, int tid) {
    float* arow = sbuf;                       // 8*512 floats
    for (int i = tid; i < 8 * 512; i += 256) arow[i] = a[i];
    __syncthreads();

    const int c = tid & 31;
    const int kg = tid >> 5;                  // 0..7
    const int col = colbase + c;
    const float* wptr = Wp + (size_t)(kg * 64) * 512 + col;
    const float* ar = arow + kg * 64;

    float acc[8];
#pragma unroll
    for (int r = 0; r < 8; r++) acc[r] = 0.f;

#pragma unroll 1
    for (int kk = 0; kk < 64; kk += 8) {
        float w[8];
#pragma unroll
        for (int u = 0; u < 8; u++) w[u] = wptr[(size_t)(kk + u) * 512];
#pragma unroll
        for (int u = 0; u < 8; u++)
#pragma unroll
            for (int r = 0; r < 8; r++)
                acc[r] += ar[r * 512 + kk + u] * w[u];
    }

    __syncthreads();
    float* red = sbuf;                        // 8*8*32 floats
#pragma unroll
    for (int r = 0; r < 8; r++)
        red[(kg * 8 + r) * 32 + c] = acc[r];
    __syncthreads();

    {
        const int r = tid >> 5, cc = tid & 31;
        if (r < 8) {
            float s = 0.f;
#pragma unroll
            for (int g = 0; g < 8; g++) s += red[(g * 8 + r) * 32 + cc];
            outp[r * 512 + colbase + cc] = s;
        }
    }
}

// ---------------------------------------------------------------------------
// Kernel 1 "prep": 176 blocks x 256 threads.
//   [0,48):    small-table GEMMs   [48,112): W split+transpose
//   [112,176): syntax scan (warp-shuffle Lindley prefix)
// ---------------------------------------------------------------------------
__global__ void __launch_bounds__(256)
prep_kernel(const int* __restrict__ tok,
            const float* __restrict__ nest,
            const float* __restrict__ seg,
            const float* __restrict__ W) {
    __shared__ float sbuf[4160];              // 16.6 KB
    const int bid = blockIdx.x;
    const int tid = threadIdx.x;

    if (bid < 48) {
        if (bid < 32) {                       // N table, 2 row halves
            const int rh = bid >> 4;
            const int colbase = (bid & 15) * 32;
            small_gemm_body(nest + rh * 8 * 512, W + 512 * 512,
                            g_N + rh * 8 * 512, colbase, sbuf, tid);
        } else {                              // G table
            const int colbase = (bid - 32) * 32;
            small_gemm_body(seg, W + 1024 * 512, g_G, colbase, sbuf, tid);
        }
    } else if (bid < 112) {
        // ---- W[0:512] split + transpose: 8x8 tiles of 64x64 ----
        const int tb = bid - 48;
        const int ki = tb >> 3, ni = tb & 7;
        float* St = sbuf;                     // 64 x 65
#pragma unroll
        for (int l = 0; l < 4; l++) {
            const int idx = tid + l * 256;
            const int kr = idx >> 4;
            const int c4 = idx & 15;
            float4 v = *(const float4*)(W + (size_t)(ki * 64 + kr) * 512 + ni * 64 + c4 * 4);
            St[kr * 65 + c4 * 4 + 0] = v.x;
            St[kr * 65 + c4 * 4 + 1] = v.y;
            St[kr * 65 + c4 * 4 + 2] = v.z;
            St[kr * 65 + c4 * 4 + 3] = v.w;
        }
        __syncthreads();

        const int n = tid >> 2;
        const int kg = tid & 3;
        __align__(16) __nv_bfloat162 hiu[8];
        __align__(16) __nv_bfloat162 lou[8];
#pragma unroll
        for (int e = 0; e < 16; e += 2) {
            float f0 = St[(kg * 16 + e) * 65 + n];
            float f1 = St[(kg * 16 + e + 1) * 65 + n];
            __nv_bfloat16 h0 = __float2bfloat16_rn(f0);
            __nv_bfloat16 h1 = __float2bfloat16_rn(f1);
            __nv_bfloat16 l0 = __float2bfloat16_rn(f0 - __bfloat162float(h0));
            __nv_bfloat16 l1 = __float2bfloat16_rn(f1 - __bfloat162float(h1));
            hiu[e >> 1] = __nv_bfloat162(h0, h1);
            lou[e >> 1] = __nv_bfloat162(l0, l1);
        }
        const size_t off = (size_t)(ni * 64 + n) * 512 + ki * 64 + kg * 16;
        *(uint4*)(g_Wthi + off) = ((uint4*)hiu)[0];
        *(uint4*)(g_Wthi + off + 8) = ((uint4*)hiu)[1];
        *(uint4*)(g_Wtlo + off) = ((uint4*)lou)[0];
        *(uint4*)(g_Wtlo + off + 8) = ((uint4*)lou)[1];
    } else {
        // ---- syntax scan with warp-shuffle parallel prefix ----
        int* sh_tok = (int*)sbuf;
        int* wsum = (int*)sbuf + 2048;
        int* wmin = wsum + 8;
        int* wcnt = wmin + 8;

        const int b = bid - 112;
        const int* t = tok + b * SS;
        for (int i = tid; i < SS; i += 256) sh_tok[i] = t[i];
        __syncthreads();

        const int base = tid * 8;
        int s = 0, mn = 0, cnt = 0;
#pragma unroll
        for (int e = 0; e < 8; e++) {
            int tk = sh_tok[base + e];
            int op = (tk == 40) | (tk == 123) | (tk == 91);
            int cl = (tk == 41) | (tk == 125) | (tk == 93);
            s += op - cl;
            mn = min(mn, s);
            cnt += (tk > 39990);
        }

        const int lane = tid & 31;
        const int wid = tid >> 5;
        int Si = s, Mi = mn, Ci = cnt;
#pragma unroll
        for (int d = 1; d < 32; d <<= 1) {
            int So = __shfl_up_sync(0xffffffffu, Si, d);
            int Mo = __shfl_up_sync(0xffffffffu, Mi, d);
            int Co = __shfl_up_sync(0xffffffffu, Ci, d);
            if (lane >= d) { Mi = min(Mo, So + Mi); Si = So + Si; Ci = Co + Ci; }
        }
        if (lane == 31) { wsum[wid] = Si; wmin[wid] = Mi; wcnt[wid] = Ci; }

        int Se = __shfl_up_sync(0xffffffffu, Si, 1);
        int Me = __shfl_up_sync(0xffffffffu, Mi, 1);
        int Ce = __shfl_up_sync(0xffffffffu, Ci, 1);
        if (lane == 0) { Se = 0; Me = 0; Ce = 0; }
        __syncthreads();

        int Sw = 0, Mw = 0, Cw = 0;
        for (int w = 0; w < wid; w++) {
            Mw = min(Mw, Sw + wmin[w]);
            Sw += wsum[w];
            Cw += wcnt[w];
        }
        int S_pre = Sw + Se;
        int M_pre = min(Mw, Sw + Me);
        int C_pre = Cw + Ce;

        s = S_pre; mn = M_pre; cnt = C_pre;
        unsigned char* out = g_combo + b * SS + base;
#pragma unroll
        for (int e = 0; e < 8; e++) {
            int tk = sh_tok[base + e];
            int op = (tk == 40) | (tk == 123) | (tk == 91);
            int cl = (tk == 41) | (tk == 125) | (tk == 93);
            s += op - cl;
            mn = min(mn, s);
            cnt += (tk > 39990);
            int lvl = min(s - mn, 15);
            out[e] = (unsigned char)((lvl << 3) | (cnt & 7));
        }
    }
}

// ---------------------------------------------------------------------------
// Kernel 2 "mega": fused GEMM + combine, 512 threads/CTA, grid 128.
// BM=128, BN=64, BK=32. 16 warps as 8(m) x 2(n), warp tile 16x32.
// Split-bf16 3-term mma (A split in-register from f32). Epilogue: tile
// staged to smem, hoisted to regs, per-batch table add + STG.128 streaming.
// ---------------------------------------------------------------------------
#define GSTRIDE 40        // padded smem row stride for BK=32 (bf16)
// smem union (max 47104 B, static):
//   mma:  As_hi [0,10240) As_lo [10240,20480) Bs_hi [20480,25600) Bs_lo [25600,30720)
//   epi:  tileS [0,32768) Ns [32768,36864) Gs [36864,38912) sc [38912,47104)
__global__ void __launch_bounds__(512)
mega_kernel(const float* __restrict__ A, float* __restrict__ out) {
    __shared__ __align__(16) char smem_raw[47104];
    __nv_bfloat16* As_hi = (__nv_bfloat16*)smem_raw;
    __nv_bfloat16* As_lo = (__nv_bfloat16*)(smem_raw + 10240);
    __nv_bfloat16* Bs_hi = (__nv_bfloat16*)(smem_raw + 20480);
    __nv_bfloat16* Bs_lo = (__nv_bfloat16*)(smem_raw + 25600);

    const int tid = threadIdx.x;
    const int q = blockIdx.x;            // 0..127
    const int n0 = (q >> 4) * 64;        // h band
    const int m0 = (q & 15) * 128;       // s tile (128 rows)

    const int wid = tid >> 5;
    const int lane = tid & 31;
    const int wm = (wid & 7) * 16;       // warp m offset (0..112)
    const int wn = (wid >> 3) * 32;      // warp n offset (0/32)

    // B staging: threads [0,256) load hi, [256,512) load lo
    const bool bhalf = (tid >= 256);
    const int btid = tid & 255;
    const int brow = btid >> 2;          // 0..63
    const int bcol = (btid & 3) * 8;     // bf16 col
    const __nv_bfloat16* Wsrc = bhalf ? g_Wtlo : g_Wthi;
    __nv_bfloat16* Bdst = bhalf ? Bs_lo : Bs_hi;

    const int r = lane >> 2;
    const int c = (lane & 3) * 2;
    const int n2 = (lane & 3) * 2;

    float acc[4][4];
#pragma unroll
    for (int j = 0; j < 4; j++)
#pragma unroll
        for (int p = 0; p < 4; p++) acc[j][p] = 0.f;

    // prefetch k-tile 0
    float4 fa[2];
    uint4 wb;
#pragma unroll
    for (int l = 0; l < 2; l++) {
        const int idx = tid + l * 512;             // < 1024
        fa[l] = *(const float4*)(A + (size_t)(m0 + (idx >> 3)) * 512 + (idx & 7) * 4);
    }
    wb = *(const uint4*)(Wsrc + (size_t)(n0 + brow) * 512 + bcol);

#pragma unroll 1
    for (int t = 0; t < 16; t++) {
        __syncthreads();
        // stage A (split f32 -> hi/lo bf16 in-register) and B tiles
#pragma unroll
        for (int l = 0; l < 2; l++) {
            const int idx = tid + l * 512;
            const int arow = idx >> 3;
            const int ac = (idx & 7) * 4;
            float4 v = fa[l];
            __nv_bfloat16 hx = __float2bfloat16_rn(v.x);
            __nv_bfloat16 hy = __float2bfloat16_rn(v.y);
            __nv_bfloat16 hz = __float2bfloat16_rn(v.z);
            __nv_bfloat16 hw = __float2bfloat16_rn(v.w);
            *(__nv_bfloat162*)(As_hi + arow * GSTRIDE + ac) = __nv_bfloat162(hx, hy);
            *(__nv_bfloat162*)(As_hi + arow * GSTRIDE + ac + 2) = __nv_bfloat162(hz, hw);
            __nv_bfloat16 lx = __float2bfloat16_rn(v.x - __bfloat162float(hx));
            __nv_bfloat16 ly = __float2bfloat16_rn(v.y - __bfloat162float(hy));
            __nv_bfloat16 lz = __float2bfloat16_rn(v.z - __bfloat162float(hz));
            __nv_bfloat16 lw = __float2bfloat16_rn(v.w - __bfloat162float(hw));
            *(__nv_bfloat162*)(As_lo + arow * GSTRIDE + ac) = __nv_bfloat162(lx, ly);
            *(__nv_bfloat162*)(As_lo + arow * GSTRIDE + ac + 2) = __nv_bfloat162(lz, lw);
        }
        *(uint4*)(Bdst + brow * GSTRIDE + bcol) = wb;
        __syncthreads();

        if (t < 15) {
            const int k0 = (t + 1) * 32;
#pragma unroll
            for (int l = 0; l < 2; l++) {
                const int idx = tid + l * 512;
                fa[l] = *(const float4*)(A + (size_t)(m0 + (idx >> 3)) * 512 + k0 + (idx & 7) * 4);
            }
            wb = *(const uint4*)(Wsrc + (size_t)(n0 + brow) * 512 + k0 + bcol);
        }

#pragma unroll
        for (int kk = 0; kk < 32; kk += 16) {
            unsigned int ah0, ah1, ah2, ah3, al0, al1, al2, al3;
            ah0 = *(const unsigned int*)(As_hi + (wm + r) * GSTRIDE + kk + c);
            ah1 = *(const unsigned int*)(As_hi + (wm + r + 8) * GSTRIDE + kk + c);
            ah2 = *(const unsigned int*)(As_hi + (wm + r) * GSTRIDE + kk + c + 8);
            ah3 = *(const unsigned int*)(As_hi + (wm + r + 8) * GSTRIDE + kk + c + 8);
            al0 = *(const unsigned int*)(As_lo + (wm + r) * GSTRIDE + kk + c);
            al1 = *(const unsigned int*)(As_lo + (wm + r + 8) * GSTRIDE + kk + c);
            al2 = *(const unsigned int*)(As_lo + (wm + r) * GSTRIDE + kk + c + 8);
            al3 = *(const unsigned int*)(As_lo + (wm + r + 8) * GSTRIDE + kk + c + 8);
#pragma unroll
            for (int j = 0; j < 4; j++) {
                const int n = wn + j * 8 + r;
                unsigned int bh0 = *(const unsigned int*)(Bs_hi + n * GSTRIDE + kk + c);
                unsigned int bh1 = *(const unsigned int*)(Bs_hi + n * GSTRIDE + kk + c + 8);
                unsigned int bl0 = *(const unsigned int*)(Bs_lo + n * GSTRIDE + kk + c);
                unsigned int bl1 = *(const unsigned int*)(Bs_lo + n * GSTRIDE + kk + c + 8);
                asm volatile(
                    "mma.sync.aligned.m16n8k16.row.col.f32.bf16.bf16.f32 "
                    "{%0,%1,%2,%3}, {%4,%5,%6,%7}, {%8,%9}, {%0,%1,%2,%3};"
                    : "+f"(acc[j][0]), "+f"(acc[j][1]), "+f"(acc[j][2]), "+f"(acc[j][3])
                    : "r"(ah0), "r"(ah1), "r"(ah2), "r"(ah3), "r"(bh0), "r"(bh1));
                asm volatile(
                    "mma.sync.aligned.m16n8k16.row.col.f32.bf16.bf16.f32 "
                    "{%0,%1,%2,%3}, {%4,%5,%6,%7}, {%8,%9}, {%0,%1,%2,%3};"
                    : "+f"(acc[j][0]), "+f"(acc[j][1]), "+f"(acc[j][2]), "+f"(acc[j][3])
                    : "r"(al0), "r"(al1), "r"(al2), "r"(al3), "r"(bh0), "r"(bh1));
                asm volatile(
                    "mma.sync.aligned.m16n8k16.row.col.f32.bf16.bf16.f32 "
                    "{%0,%1,%2,%3}, {%4,%5,%6,%7}, {%8,%9}, {%0,%1,%2,%3};"
                    : "+f"(acc[j][0]), "+f"(acc[j][1]), "+f"(acc[j][2]), "+f"(acc[j][3])
                    : "r"(ah0), "r"(ah1), "r"(ah2), "r"(ah3), "r"(bl0), "r"(bl1));
            }
        }
    }

    // ---------------- epilogue ----------------
    __syncthreads();            // mma smem reads done; reuse smem

    float* tileS = (float*)smem_raw;                           // 128 x 64
    float* Ns = (float*)(smem_raw + 32768);                    // 16 x 64
    float* Gs = (float*)(smem_raw + 36864);                    // 8 x 64
    unsigned char* sc = (unsigned char*)(smem_raw + 38912);    // 64 b x 128 rows

    // stage acc tile
#pragma unroll
    for (int j = 0; j < 4; j++) {
        *(float2*)(tileS + (wm + r) * 64 + wn + j * 8 + n2) =
            make_float2(acc[j][0], acc[j][1]);
        *(float2*)(tileS + (wm + r + 8) * 64 + wn + j * 8 + n2) =
            make_float2(acc[j][2], acc[j][3]);
    }
    // stage table slices + combo
#pragma unroll
    for (int l = 0; l < 2; l++) {
        const int i = tid + l * 512;                           // 0..1023
        Ns[i] = g_N[(i >> 6) * 512 + n0 + (i & 63)];
    }
    Gs[tid & 511] = g_G[((tid & 511) >> 6) * 512 + n0 + (tid & 63)];
    {
        const int b = tid >> 3;                                // 0..63
        const int part = tid & 7;                              // 0..7 (x16B)
        *(uint4*)(sc + b * 128 + part * 16) =
            *(const uint4*)(g_combo + b * SS + m0 + part * 16);
    }
    __syncthreads();

    // re-partition: thread = (row = tid>>2, 0..127) x 4 float4 cols
    const int row = tid >> 2;
    const int c4b = tid & 3;
    float4 tv[4];
#pragma unroll
    for (int k4 = 0; k4 < 4; k4++)
        tv[k4] = *(const float4*)(tileS + row * 64 + (c4b + k4 * 4) * 4);

    float4* out4 = (float4*)out;
    const unsigned rowbase = (m0 + row) * 128 + (n0 >> 2) + c4b;
#pragma unroll 2
    for (int b = 0; b < BB; b++) {
        const int cc = sc[b * 128 + row];
        const float* nrow = Ns + (cc >> 3) * 64;
        const float* grow = Gs + (cc & 7) * 64;
        const unsigned obase = b * (SS * 128u) + rowbase;
#pragma unroll
        for (int k4 = 0; k4 < 4; k4++) {
            const int col = (c4b + k4 * 4) * 4;
            float4 nv = *(const float4*)(nrow + col);
            float4 gv = *(const float4*)(grow + col);
            float4 o;
            o.x = tv[k4].x + nv.x + gv.x;
            o.y = tv[k4].y + nv.y + gv.y;
            o.z = tv[k4].z + nv.z + gv.z;
            o.w = tv[k4].w + nv.w + gv.w;
            __stcs(out4 + obase + k4 * 4, o);
        }
    }
}

// ---------------------------------------------------------------------------
extern "C" void kernel_launch(void* const* d_in, const int* in_sizes, int n_in,
                              void* d_out, int out_size) {
    const int*   tok  = (const int*)d_in[0];    // token_ids [64,2048] int32
    const float* pos  = (const float*)d_in[1];  // pos_table [2048,512]
    const float* nest = (const float*)d_in[2];  // nest_table [16,512]
    const float* seg  = (const float*)d_in[3];  // seg_table [8,512]
    const float* W    = (const float*)d_in[4];  // W [1536,512]
    float* out = (float*)d_out;                 // [64,2048,512] f32

    prep_kernel<<<176, 256>>>(tok, nest, seg, W);
    mega_kernel<<<128, 512>>>(pos, out);
}